// round 12
// baseline (speedup 1.0000x reference)
#include <cuda_runtime.h>
#include <cuda_bf16.h>
#include <cstdint>
#include <cstddef>
#include <math.h>

// Problem constants
#define B_    2
#define CDIM  256
#define NTOK  32768          // 32*32*32 tokens
#define HEADS 8
#define DH    32
#define O1    768            // 3 * HEADS * DH

// GEMM tiling
#define BM 128
#define BN 128
#define BK 32
#define APITCH 40            // 32 + 8 bf16 pad  (80B rows -> conflict-free ldmatrix)
#define BPITCH 136           // 128 + 8 bf16 pad (272B rows -> conflict-free ldmatrix.trans)
#define OA_H 0
#define OA_L (BM*APITCH)                 // 5120
#define OB_H (2*BM*APITCH)               // 10240
#define OB_L (2*BM*APITCH + BK*BPITCH)   // 14592
#define BUFE (2*BM*APITCH + 2*BK*BPITCH) // 18944 bf16 elems per stage
#define GEMM_SMEM (2*BUFE*2)             // bytes (double buffered) = 75776
#define EPI_PITCH 129                    // fp32 epilogue scratch pitch

// ---------------------------------------------------------------------------
// Scratch (device globals; no cudaMalloc allowed)
// ---------------------------------------------------------------------------
__device__ float g_ksum[B_ * 256];
__device__ float g_ksum_part[B_ * 256 * 256];                    // [b][krow][ntile]
__device__ float g_ctx_part[(size_t)B_ * HEADS * 256 * DH * DH];
__device__ float g_ctx[B_ * HEADS * DH * DH];
__device__ __align__(16) __nv_bfloat16 g_ekh[(size_t)B_*CDIM*NTOK];  // exp(k) hi
__device__ __align__(16) __nv_bfloat16 g_ekl[(size_t)B_*CDIM*NTOK];  // exp(k) lo
__device__ __align__(16) __nv_bfloat16 g_vh [(size_t)B_*CDIM*NTOK];  // v hi
__device__ __align__(16) __nv_bfloat16 g_vl [(size_t)B_*CDIM*NTOK];  // v lo
__device__ __align__(16) __nv_bfloat16 g_qh[(size_t)B_*CDIM*NTOK];
__device__ __align__(16) __nv_bfloat16 g_ql[(size_t)B_*CDIM*NTOK];
__device__ __align__(16) __nv_bfloat16 g_wh[O1*CDIM];
__device__ __align__(16) __nv_bfloat16 g_wl[O1*CDIM];
__device__ __align__(16) __nv_bfloat16 g_w2h[B_*CDIM*CDIM];
__device__ __align__(16) __nv_bfloat16 g_w2l[B_*CDIM*CDIM];

// ---------------------------------------------------------------------------
// PTX helpers
// ---------------------------------------------------------------------------
#define CP16(dst, src) \
    asm volatile("cp.async.cg.shared.global [%0], [%1], 16;" :: "r"(dst), "l"(src) : "memory")
#define CP_COMMIT() asm volatile("cp.async.commit_group;" ::: "memory")
#define CP_WAIT0()  asm volatile("cp.async.wait_group 0;"  ::: "memory")

#define LDSM4(r0,r1,r2,r3,a) \
    asm volatile("ldmatrix.sync.aligned.m8n8.x4.shared.b16 {%0,%1,%2,%3}, [%4];" \
                 : "=r"(r0),"=r"(r1),"=r"(r2),"=r"(r3) : "r"(a))
#define LDSM4T(r0,r1,r2,r3,a) \
    asm volatile("ldmatrix.sync.aligned.m8n8.x4.trans.shared.b16 {%0,%1,%2,%3}, [%4];" \
                 : "=r"(r0),"=r"(r1),"=r"(r2),"=r"(r3) : "r"(a))

#define MMA3(d, a, b) \
    asm volatile("mma.sync.aligned.m16n8k16.row.col.f32.bf16.bf16.f32 " \
                 "{%0,%1,%2,%3},{%4,%5,%6,%7},{%8,%9},{%0,%1,%2,%3};" \
                 : "+f"((d)[0]),"+f"((d)[1]),"+f"((d)[2]),"+f"((d)[3]) \
                 : "r"((a)[0]),"r"((a)[1]),"r"((a)[2]),"r"((a)[3]), \
                   "r"((b)[0]),"r"((b)[1]))

__device__ __forceinline__ uint32_t pack_bf16x2(float a, float b)
{
    __nv_bfloat162 p;
    p.x = __float2bfloat16(a);
    p.y = __float2bfloat16(b);
    return *(uint32_t*)&p;
}
__device__ __forceinline__ uint32_t pack_bf16x2_lo(float a, float b, uint32_t hi)
{
    __nv_bfloat162 h = *(__nv_bfloat162*)&hi;
    __nv_bfloat162 p;
    p.x = __float2bfloat16(a - __bfloat162float(h.x));
    p.y = __float2bfloat16(b - __bfloat162float(h.y));
    return *(uint32_t*)&p;
}

// ---------------------------------------------------------------------------
// Split-bf16 tensor-core GEMM. C[M,N] = A[M,K] * B[K,N]; 3-term split
// (ah*bh + ah*bl + al*bh), 128x128x32 tiles, 8 warps, m16n8k16 MMAs.
// MODE 1 (GEMM1): B is fp32 (x), converted to bf16 hi/lo in-kernel.
//   Fused epilogues: blockIdx.y 0-1 q-softmax -> g_qh/g_ql bf16;
//   2-3 exp(k) -> g_ekh/g_ekl bf16 pairs + row sums; 4-5 v -> g_vh/g_vl.
// MODE 0 (GEMM3): B is pre-split bf16 hi/lo (q); plain fp32 epilogue -> C.
// ---------------------------------------------------------------------------
template <int MODE>
__global__ __launch_bounds__(256, 2)
void gemm_bf16split(const __nv_bfloat16* __restrict__ Ah, const __nv_bfloat16* __restrict__ Al,
                    const __nv_bfloat16* __restrict__ Bh, const __nv_bfloat16* __restrict__ Bl,
                    const float* __restrict__ Bf,
                    float* __restrict__ C, int K, int N,
                    long sA, long sB, long sC)
{
    extern __shared__ __nv_bfloat16 smbuf[];
    const int bz = blockIdx.z;
    Ah += bz * sA;  Al += bz * sA;
    if (MODE == 0) { Bh += bz * sB;  Bl += bz * sB; }
    else           { Bf += bz * sB; }
    C  += bz * sC;

    const int tid   = threadIdx.x;
    const int lane  = tid & 31;
    const int wid   = tid >> 5;
    const int warp_m = wid >> 2;
    const int warp_n = wid & 3;
    const int bn = blockIdx.x * BN;
    const int bm = blockIdx.y * BM;

    const uint32_t su = (uint32_t)__cvta_generic_to_shared(smbuf);

    const int rowA = (lane & 7) + ((lane >> 3) & 1) * 8;
    const int colA = (lane >> 4) * 8;
    const uint32_t aOff = (uint32_t)(((warp_m * 64 + rowA) * APITCH + colA) * 2);
    const int rowB = (lane & 7) + ((lane >> 3) & 1) * 8;
    const int colB = warp_n * 32 + ((lane >> 4) & 1) * 8;
    const uint32_t bOff = (uint32_t)((rowB * BPITCH + colB) * 2);

    float acc[4][4][4];
#pragma unroll
    for (int i = 0; i < 4; i++)
#pragma unroll
        for (int j = 0; j < 4; j++)
#pragma unroll
            for (int r = 0; r < 4; r++) acc[i][j][r] = 0.f;

    float4 breg[4];

#define LOAD_A(buf, kt) do {                                                         \
    _Pragma("unroll")                                                                \
    for (int p = 0; p < 2; p++) {                                                    \
        int id = tid + p * 256;                                                      \
        int ra = id >> 2, ca = (id & 3) * 8;                                         \
        uint32_t dA = su + (uint32_t)(((buf)*BUFE + ra*APITCH + ca) * 2);            \
        CP16(dA + OA_H*2, Ah + (long)(bm + ra) * K + (kt) + ca);                     \
        CP16(dA + OA_L*2, Al + (long)(bm + ra) * K + (kt) + ca);                     \
    }                                                                                \
} while (0)

#define LOAD_B0(buf, kt) do {                                                        \
    _Pragma("unroll")                                                                \
    for (int p = 0; p < 2; p++) {                                                    \
        int id = tid + p * 256;                                                      \
        int rb = id >> 4, cb = (id & 15) * 8;                                        \
        uint32_t dB = su + (uint32_t)(((buf)*BUFE + rb*BPITCH + cb) * 2);            \
        CP16(dB + OB_H*2, Bh + (long)((kt) + rb) * N + bn + cb);                     \
        CP16(dB + OB_L*2, Bl + (long)((kt) + rb) * N + bn + cb);                     \
    }                                                                                \
} while (0)

#define LDG_B(kt) do {                                                               \
    _Pragma("unroll")                                                                \
    for (int p = 0; p < 4; p++) {                                                    \
        int id = tid + p * 256;                                                      \
        int rb = id >> 5, cb = (id & 31) * 4;                                        \
        breg[p] = *(const float4*)(Bf + (long)((kt) + rb) * N + bn + cb);            \
    }                                                                                \
} while (0)

#define CVT_STS_B(buf) do {                                                          \
    _Pragma("unroll")                                                                \
    for (int p = 0; p < 4; p++) {                                                    \
        int id = tid + p * 256;                                                      \
        int rb = id >> 5, cb = (id & 31) * 4;                                        \
        float vv[4] = {breg[p].x, breg[p].y, breg[p].z, breg[p].w};                  \
        __nv_bfloat16 hb4[4], lb4[4];                                                \
        _Pragma("unroll")                                                            \
        for (int j = 0; j < 4; j++) {                                                \
            hb4[j] = __float2bfloat16(vv[j]);                                        \
            lb4[j] = __float2bfloat16(vv[j] - __bfloat162float(hb4[j]));             \
        }                                                                            \
        __nv_bfloat16* bp = smbuf + (buf)*BUFE + rb*BPITCH + cb;                     \
        *(uint2*)(bp + OB_H) = *(uint2*)hb4;                                         \
        *(uint2*)(bp + OB_L) = *(uint2*)lb4;                                         \
    }                                                                                \
} while (0)

    LOAD_A(0, 0);
    if (MODE == 0) LOAD_B0(0, 0);
    CP_COMMIT();
    if (MODE == 1) LDG_B(0);
    CP_WAIT0();
    if (MODE == 1) CVT_STS_B(0);
    __syncthreads();

    int buf = 0;
    for (int kt = BK; kt <= K; kt += BK) {
        if (kt < K) {
            LOAD_A(buf ^ 1, kt);
            if (MODE == 0) LOAD_B0(buf ^ 1, kt);
            CP_COMMIT();
            if (MODE == 1) LDG_B(kt);
        }

        const uint32_t stage = su + (uint32_t)(buf * BUFE * 2);
#pragma unroll
        for (int kk = 0; kk < BK; kk += 16) {
            uint32_t fbh[4][2], fbl[4][2];
#pragma unroll
            for (int pr = 0; pr < 2; pr++) {
                uint32_t adH = stage + (uint32_t)(OB_H*2) + (uint32_t)(kk*BPITCH*2) + bOff + (uint32_t)(pr*32);
                LDSM4T(fbh[2*pr][0], fbh[2*pr][1], fbh[2*pr+1][0], fbh[2*pr+1][1], adH);
                uint32_t adL = stage + (uint32_t)(OB_L*2) + (uint32_t)(kk*BPITCH*2) + bOff + (uint32_t)(pr*32);
                LDSM4T(fbl[2*pr][0], fbl[2*pr][1], fbl[2*pr+1][0], fbl[2*pr+1][1], adL);
            }
#pragma unroll
            for (int mt = 0; mt < 4; mt++) {
                uint32_t fah[4], fal[4];
                uint32_t aaH = stage + (uint32_t)(OA_H*2) + aOff + (uint32_t)((mt*16*APITCH + kk) * 2);
                LDSM4(fah[0], fah[1], fah[2], fah[3], aaH);
                uint32_t aaL = stage + (uint32_t)(OA_L*2) + aOff + (uint32_t)((mt*16*APITCH + kk) * 2);
                LDSM4(fal[0], fal[1], fal[2], fal[3], aaL);
#pragma unroll
                for (int nt = 0; nt < 4; nt++) {
                    MMA3(acc[mt][nt], fah, fbh[nt]);
                    MMA3(acc[mt][nt], fah, fbl[nt]);
                    MMA3(acc[mt][nt], fal, fbh[nt]);
                }
            }
        }

        if (kt < K) {
            CP_WAIT0();
            if (MODE == 1) CVT_STS_B(buf ^ 1);
            __syncthreads();
            buf ^= 1;
        }
    }
#undef LOAD_A
#undef LOAD_B0
#undef LDG_B
#undef CVT_STS_B

    const int r0 = warp_m * 64 + (lane >> 2);
    const int c0 = warp_n * 32 + (lane & 3) * 2;

    if (MODE == 1 && blockIdx.y < 2) {
        // ---- q path: softmax over d, write bf16 hi/lo ----
        __syncthreads();
        float* sf = (float*)smbuf;
#pragma unroll
        for (int mt = 0; mt < 4; mt++)
#pragma unroll
            for (int nt = 0; nt < 4; nt++) {
                int r = r0 + mt * 16, c = c0 + nt * 8;
                sf[r * EPI_PITCH + c]           = acc[mt][nt][0];
                sf[r * EPI_PITCH + c + 1]       = acc[mt][nt][1];
                sf[(r + 8) * EPI_PITCH + c]     = acc[mt][nt][2];
                sf[(r + 8) * EPI_PITCH + c + 1] = acc[mt][nt][3];
            }
        __syncthreads();

        const int col = tid & 127;
        const int h0  = tid >> 7;
        const long n  = bn + col;
#pragma unroll
        for (int hh = h0; hh < 4; hh += 2) {
            float v[DH];
            float mx = -1e30f;
#pragma unroll
            for (int d = 0; d < DH; d++) {
                v[d] = sf[(hh * DH + d) * EPI_PITCH + col];
                mx = fmaxf(mx, v[d]);
            }
            float s = 0.f;
#pragma unroll
            for (int d = 0; d < DH; d++) { v[d] = expf(v[d] - mx); s += v[d]; }
            float inv = 1.f / s;
            const int hglob = blockIdx.y * 4 + hh;
            __nv_bfloat16* qh = g_qh + ((long)bz * CDIM + hglob * DH) * NTOK + n;
            __nv_bfloat16* ql = g_ql + ((long)bz * CDIM + hglob * DH) * NTOK + n;
#pragma unroll
            for (int d = 0; d < DH; d++) {
                float q = v[d] * inv;
                __nv_bfloat16 hb = __float2bfloat16(q);
                qh[(long)d * NTOK] = hb;
                ql[(long)d * NTOK] = __float2bfloat16(q - __bfloat162float(hb));
            }
        }
    } else if (MODE == 1 && blockIdx.y < 4) {
        // ---- k path: exp -> bf16 hi/lo pairs + partial row sums ----
        __syncthreads();
        float* sf = (float*)smbuf;
#pragma unroll
        for (int mt = 0; mt < 4; mt++)
#pragma unroll
            for (int nt = 0; nt < 4; nt++) {
                int r = r0 + mt * 16, c = c0 + nt * 8;
                float e0 = expf(acc[mt][nt][0]);
                float e1 = expf(acc[mt][nt][1]);
                float e2 = expf(acc[mt][nt][2]);
                float e3 = expf(acc[mt][nt][3]);
                long kr = (blockIdx.y - 2) * 128;
                long i01 = ((long)bz * CDIM + kr + r) * NTOK + bn + c;
                long i23 = i01 + 8L * NTOK;
                uint32_t h01 = pack_bf16x2(e0, e1);
                uint32_t h23 = pack_bf16x2(e2, e3);
                *(uint32_t*)(g_ekh + i01) = h01;
                *(uint32_t*)(g_ekl + i01) = pack_bf16x2_lo(e0, e1, h01);
                *(uint32_t*)(g_ekh + i23) = h23;
                *(uint32_t*)(g_ekl + i23) = pack_bf16x2_lo(e2, e3, h23);
                sf[r * EPI_PITCH + c]           = e0;
                sf[r * EPI_PITCH + c + 1]       = e1;
                sf[(r + 8) * EPI_PITCH + c]     = e2;
                sf[(r + 8) * EPI_PITCH + c + 1] = e3;
            }
        __syncthreads();
        if (tid < 128) {
            float s = 0.f;
#pragma unroll 8
            for (int c = 0; c < 128; c++) s += sf[tid * EPI_PITCH + c];
            int kr = (blockIdx.y - 2) * 128 + tid;
            g_ksum_part[((long)bz * 256 + kr) * 256 + blockIdx.x] = s;
        }
    } else if (MODE == 1) {
        // ---- v path: bf16 hi/lo pairs ----
#pragma unroll
        for (int mt = 0; mt < 4; mt++)
#pragma unroll
            for (int nt = 0; nt < 4; nt++) {
                int r = r0 + mt * 16, c = c0 + nt * 8;
                long vr = (blockIdx.y - 4) * 128;
                long i01 = ((long)bz * CDIM + vr + r) * NTOK + bn + c;
                long i23 = i01 + 8L * NTOK;
                uint32_t h01 = pack_bf16x2(acc[mt][nt][0], acc[mt][nt][1]);
                uint32_t h23 = pack_bf16x2(acc[mt][nt][2], acc[mt][nt][3]);
                *(uint32_t*)(g_vh + i01) = h01;
                *(uint32_t*)(g_vl + i01) = pack_bf16x2_lo(acc[mt][nt][0], acc[mt][nt][1], h01);
                *(uint32_t*)(g_vh + i23) = h23;
                *(uint32_t*)(g_vl + i23) = pack_bf16x2_lo(acc[mt][nt][2], acc[mt][nt][3], h23);
            }
    } else {
        // ---- plain fp32 store (GEMM3 output) ----
#pragma unroll
        for (int mt = 0; mt < 4; mt++)
#pragma unroll
            for (int nt = 0; nt < 4; nt++) {
                long row = bm + r0 + mt * 16;
                float* cp = C + row * (long)N + bn + c0 + nt * 8;
                *(float2*)cp               = make_float2(acc[mt][nt][0], acc[mt][nt][1]);
                *(float2*)(cp + 8*(long)N) = make_float2(acc[mt][nt][2], acc[mt][nt][3]);
            }
    }
}

// ---------------------------------------------------------------------------
// fp32 -> (bf16 hi, bf16 lo) split conversion (weights only).
// ---------------------------------------------------------------------------
__global__ void cvt_split(const float* __restrict__ src,
                          __nv_bfloat16* __restrict__ h, __nv_bfloat16* __restrict__ l,
                          long n)
{
    long i = ((long)blockIdx.x * blockDim.x + threadIdx.x) * 4;
    if (i >= n) return;
    float4 v = *(const float4*)(src + i);
    float a[4] = {v.x, v.y, v.z, v.w};
#pragma unroll
    for (int j = 0; j < 4; j++) {
        __nv_bfloat16 hh = __float2bfloat16(a[j]);
        h[i + j] = hh;
        l[i + j] = __float2bfloat16(a[j] - __bfloat162float(hh));
    }
}

// ---------------------------------------------------------------------------
// Reduce per-ntile partial k row sums. Deterministic.
// ---------------------------------------------------------------------------
__global__ void ksum_reduce_kernel()
{
    int b  = blockIdx.x >> 8;
    int kr = blockIdx.x & 255;
    __shared__ float red[256];
    red[threadIdx.x] = g_ksum_part[((long)b * 256 + kr) * 256 + threadIdx.x];
    __syncthreads();
    for (int o = 128; o > 0; o >>= 1) {
        if (threadIdx.x < o) red[threadIdx.x] += red[threadIdx.x + o];
        __syncthreads();
    }
    if (threadIdx.x == 0) g_ksum[b * 256 + kr] = red[0];
}

// ---------------------------------------------------------------------------
// Partial contexts via split-bf16 mma over 128-token stripes.
// ctx[d][e] = sum_n ek[d,n] * v[e,n]; A = ek [M=32ch][K=tok] row-major,
// B = v [N=32ch][K=tok] (= col-major K x N for mma row.col).
// Fragments LDG'd directly from global (no smem/ldmatrix). One warp/stripe.
// ---------------------------------------------------------------------------
__global__ __launch_bounds__(256)
void ctx_part_kernel()
{
    const int w      = threadIdx.x >> 5;
    const int lane   = threadIdx.x & 31;
    const int stripe = blockIdx.x * 8 + w;     // 0..255
    const int h      = blockIdx.y;
    const int b      = blockIdx.z;
    const int lr = lane >> 2, lc = lane & 3;

    const long chbase = ((long)b * CDIM + h * DH) * NTOK;
    const int  n0 = stripe * 128;

    float acc[2][4][4];
#pragma unroll
    for (int i = 0; i < 2; i++)
#pragma unroll
        for (int j = 0; j < 4; j++)
#pragma unroll
            for (int r = 0; r < 4; r++) acc[i][j][r] = 0.f;

#pragma unroll
    for (int c = 0; c < 4; c++) {
#pragma unroll
        for (int ks = 0; ks < 2; ks++) {
            const long tk = n0 + c * 32 + ks * 16 + lc * 2;
            uint32_t fah[2][4], fal[2][4], fbh[4][2], fbl[4][2];
#pragma unroll
            for (int mt = 0; mt < 2; mt++) {
                long r0i = chbase + (long)(mt * 16 + lr) * NTOK + tk;
                long r8i = r0i + 8L * NTOK;
                fah[mt][0] = *(const uint32_t*)(g_ekh + r0i);
                fah[mt][1] = *(const uint32_t*)(g_ekh + r8i);
                fah[mt][2] = *(const uint32_t*)(g_ekh + r0i + 8);
                fah[mt][3] = *(const uint32_t*)(g_ekh + r8i + 8);
                fal[mt][0] = *(const uint32_t*)(g_ekl + r0i);
                fal[mt][1] = *(const uint32_t*)(g_ekl + r8i);
                fal[mt][2] = *(const uint32_t*)(g_ekl + r0i + 8);
                fal[mt][3] = *(const uint32_t*)(g_ekl + r8i + 8);
            }
#pragma unroll
            for (int nt = 0; nt < 4; nt++) {
                long rbi = chbase + (long)(nt * 8 + lr) * NTOK + tk;
                fbh[nt][0] = *(const uint32_t*)(g_vh + rbi);
                fbh[nt][1] = *(const uint32_t*)(g_vh + rbi + 8);
                fbl[nt][0] = *(const uint32_t*)(g_vl + rbi);
                fbl[nt][1] = *(const uint32_t*)(g_vl + rbi + 8);
            }
#pragma unroll
            for (int mt = 0; mt < 2; mt++)
#pragma unroll
                for (int nt = 0; nt < 4; nt++) {
                    MMA3(acc[mt][nt], fah[mt], fbh[nt]);
                    MMA3(acc[mt][nt], fah[mt], fbl[nt]);
                    MMA3(acc[mt][nt], fal[mt], fbh[nt]);
                }
        }
    }

    float* out = g_ctx_part + ((long)((b * HEADS + h) * 256) + stripe) * (DH * DH);
#pragma unroll
    for (int mt = 0; mt < 2; mt++)
#pragma unroll
        for (int nt = 0; nt < 4; nt++) {
            int d0 = mt * 16 + lr, e0 = nt * 8 + lc * 2;
            out[d0 * DH + e0]           = acc[mt][nt][0];
            out[d0 * DH + e0 + 1]       = acc[mt][nt][1];
            out[(d0 + 8) * DH + e0]     = acc[mt][nt][2];
            out[(d0 + 8) * DH + e0 + 1] = acc[mt][nt][3];
        }
}

__global__ void ctx_reduce_kernel()
{
    int idx = blockIdx.x * blockDim.x + threadIdx.x;  // < B_*HEADS*1024
    int de = idx % (DH * DH);
    int bh = idx / (DH * DH);
    int d  = de / DH;
    int b  = bh / HEADS, h = bh % HEADS;
    const float* p = g_ctx_part + (long)bh * 256 * (DH * DH) + de;
    float s = 0.f;
#pragma unroll 8
    for (int st = 0; st < 256; st++) s += p[(long)st * (DH * DH)];
    float inv = 1.f / g_ksum[b * 256 + h * DH + d];
    g_ctx[(long)bh * (DH * DH) + de] = s * inv;
}

// ---------------------------------------------------------------------------
// Fold w_out with context; emit bf16 hi/lo W2.
// ---------------------------------------------------------------------------
__global__ void fold_w2_kernel(const float* __restrict__ w_out)
{
    int idx = blockIdx.x * blockDim.x + threadIdx.x;  // < B_*256*256
    int hd = idx % 256;
    int o  = (idx / 256) % 256;
    int b  = idx / 65536;
    int h = hd / DH, d = hd % DH;
    const float* wrow = w_out + o * 256 + h * DH;
    const float* ctx  = g_ctx + ((long)(b * HEADS + h) * DH + d) * DH;
    float s = 0.f;
#pragma unroll
    for (int e = 0; e < DH; e++) s = fmaf(wrow[e], ctx[e], s);
    __nv_bfloat16 hh = __float2bfloat16(s);
    g_w2h[(long)b * 65536 + o * 256 + hd] = hh;
    g_w2l[(long)b * 65536 + o * 256 + hd] = __float2bfloat16(s - __bfloat162float(hh));
}

// ---------------------------------------------------------------------------
// Launch
// ---------------------------------------------------------------------------
extern "C" void kernel_launch(void* const* d_in, const int* in_sizes, int n_in,
                              void* d_out, int out_size)
{
    const float* x     = (const float*)d_in[0];  // [2,256,32768]
    const float* w_qkv = (const float*)d_in[1];  // [768,256]
    const float* w_out = (const float*)d_in[2];  // [256,256]
    float* out = (float*)d_out;                  // [2,256,32768]

    __nv_bfloat16 *qh, *ql, *wh, *wl, *w2h, *w2l;
    cudaGetSymbolAddress((void**)&qh,  g_qh);
    cudaGetSymbolAddress((void**)&ql,  g_ql);
    cudaGetSymbolAddress((void**)&wh,  g_wh);
    cudaGetSymbolAddress((void**)&wl,  g_wl);
    cudaGetSymbolAddress((void**)&w2h, g_w2h);
    cudaGetSymbolAddress((void**)&w2l, g_w2l);

    cudaFuncSetAttribute(gemm_bf16split<1>, cudaFuncAttributeMaxDynamicSharedMemorySize, GEMM_SMEM);
    cudaFuncSetAttribute(gemm_bf16split<0>, cudaFuncAttributeMaxDynamicSharedMemorySize, GEMM_SMEM);

    // 0) bf16 hi/lo split of w_qkv only
    cvt_split<<<(O1*CDIM/4 + 255)/256, 256>>>(w_qkv, wh, wl, (long)O1*CDIM);

    // 1) qkv = w_qkv @ x; fused fp32-B conversion + fused q/k/v epilogues
    gemm_bf16split<1><<<dim3(NTOK/BN, O1/BM, B_), 256, GEMM_SMEM>>>(
        wh, wl, nullptr, nullptr, x, nullptr, CDIM, NTOK,
        0L, (long)CDIM*NTOK, 0L);

    // 2) finish k row sums
    ksum_reduce_kernel<<<B_ * 256, 256>>>();

    // 3) partial contexts (tensor-core, fragment-direct loads)
    ctx_part_kernel<<<dim3(32, HEADS, B_), 256>>>();

    // 4) reduce + normalize contexts
    ctx_reduce_kernel<<<(B_ * HEADS * DH * DH) / 256, 256>>>();

    // 5) fold output weight with context -> bf16 hi/lo
    fold_w2_kernel<<<(B_ * 256 * 256) / 256, 256>>>(w_out);

    // 6) out = W2 @ q  (bf16-pair B path, plain epilogue)
    gemm_bf16split<0><<<dim3(NTOK/BN, CDIM/BM, B_), 256, GEMM_SMEM>>>(
        w2h, w2l, qh, ql, nullptr, out, CDIM, NTOK,
        (long)CDIM*CDIM, (long)CDIM*NTOK, (long)CDIM*NTOK);
}

// round 13
// speedup vs baseline: 1.1254x; 1.1254x over previous
#include <cuda_runtime.h>
#include <cuda_bf16.h>
#include <cuda_fp16.h>
#include <cstdint>
#include <cstddef>
#include <math.h>

// Problem constants
#define B_    2
#define CDIM  256
#define NTOK  32768          // 32*32*32 tokens
#define HEADS 8
#define DH    32
#define O1    768            // 3 * HEADS * DH

// GEMM tiling
#define BM 128
#define BN 128
#define BK 32
#define APITCH 40            // 32 + 8 bf16 pad  (80B rows -> conflict-free ldmatrix)
#define BPITCH 136           // 128 + 8 bf16 pad (272B rows -> conflict-free ldmatrix.trans)
#define OA_H 0
#define OA_L (BM*APITCH)                 // 5120
#define OB_H (2*BM*APITCH)               // 10240
#define OB_L (2*BM*APITCH + BK*BPITCH)   // 14592
#define BUFE (2*BM*APITCH + 2*BK*BPITCH) // 18944 bf16 elems per stage
#define GEMM_SMEM (2*BUFE*2)             // bytes (double buffered) = 75776
#define EPI_PITCH 129                    // fp32 epilogue scratch pitch

// ---------------------------------------------------------------------------
// Scratch (device globals; no cudaMalloc allowed)
// ---------------------------------------------------------------------------
__device__ float g_ksum[B_ * 256];
__device__ float g_ksum_part[B_ * 256 * 256];                    // [b][krow][ntile]
__device__ float g_ctx_part[(size_t)B_ * HEADS * 256 * DH * DH];
__device__ float g_ctx[B_ * HEADS * DH * DH];
__device__ __align__(16) __half g_ekf[(size_t)B_*CDIM*NTOK];     // exp(k) fp16
__device__ __align__(16) __half g_vf [(size_t)B_*CDIM*NTOK];     // v fp16
__device__ __align__(16) __nv_bfloat16 g_qh[(size_t)B_*CDIM*NTOK];
__device__ __align__(16) __nv_bfloat16 g_ql[(size_t)B_*CDIM*NTOK];
__device__ __align__(16) __nv_bfloat16 g_wh[O1*CDIM];
__device__ __align__(16) __nv_bfloat16 g_wl[O1*CDIM];
__device__ __align__(16) __nv_bfloat16 g_w2h[B_*CDIM*CDIM];
__device__ __align__(16) __nv_bfloat16 g_w2l[B_*CDIM*CDIM];

// ---------------------------------------------------------------------------
// PTX helpers
// ---------------------------------------------------------------------------
#define CP16(dst, src) \
    asm volatile("cp.async.cg.shared.global [%0], [%1], 16;" :: "r"(dst), "l"(src) : "memory")
#define CP_COMMIT() asm volatile("cp.async.commit_group;" ::: "memory")
#define CP_WAIT0()  asm volatile("cp.async.wait_group 0;"  ::: "memory")

#define LDSM4(r0,r1,r2,r3,a) \
    asm volatile("ldmatrix.sync.aligned.m8n8.x4.shared.b16 {%0,%1,%2,%3}, [%4];" \
                 : "=r"(r0),"=r"(r1),"=r"(r2),"=r"(r3) : "r"(a))
#define LDSM4T(r0,r1,r2,r3,a) \
    asm volatile("ldmatrix.sync.aligned.m8n8.x4.trans.shared.b16 {%0,%1,%2,%3}, [%4];" \
                 : "=r"(r0),"=r"(r1),"=r"(r2),"=r"(r3) : "r"(a))

#define MMA3(d, a, b) \
    asm volatile("mma.sync.aligned.m16n8k16.row.col.f32.bf16.bf16.f32 " \
                 "{%0,%1,%2,%3},{%4,%5,%6,%7},{%8,%9},{%0,%1,%2,%3};" \
                 : "+f"((d)[0]),"+f"((d)[1]),"+f"((d)[2]),"+f"((d)[3]) \
                 : "r"((a)[0]),"r"((a)[1]),"r"((a)[2]),"r"((a)[3]), \
                   "r"((b)[0]),"r"((b)[1]))

#define MMAH(d, a, b) \
    asm volatile("mma.sync.aligned.m16n8k16.row.col.f32.f16.f16.f32 " \
                 "{%0,%1,%2,%3},{%4,%5,%6,%7},{%8,%9},{%0,%1,%2,%3};" \
                 : "+f"((d)[0]),"+f"((d)[1]),"+f"((d)[2]),"+f"((d)[3]) \
                 : "r"((a)[0]),"r"((a)[1]),"r"((a)[2]),"r"((a)[3]), \
                   "r"((b)[0]),"r"((b)[1]))

__device__ __forceinline__ uint32_t pack_half2(float a, float b)
{
    __half2 p = __floats2half2_rn(a, b);
    return *(uint32_t*)&p;
}

// ---------------------------------------------------------------------------
// Split-bf16 tensor-core GEMM. C[M,N] = A[M,K] * B[K,N]; 3-term split
// (ah*bh + ah*bl + al*bh), 128x128x32 tiles, 8 warps, m16n8k16 MMAs.
// MODE 1 (GEMM1): B is fp32 (x), converted to bf16 hi/lo in-kernel.
//   Fused epilogues: blockIdx.y 0-1 q-softmax -> g_qh/g_ql bf16;
//   2-3 exp(k) -> g_ekf fp16 + row sums (fp32); 4-5 v -> g_vf fp16.
// MODE 0 (GEMM3): B is pre-split bf16 hi/lo (q); plain fp32 epilogue -> C.
// ---------------------------------------------------------------------------
template <int MODE>
__global__ __launch_bounds__(256, 2)
void gemm_bf16split(const __nv_bfloat16* __restrict__ Ah, const __nv_bfloat16* __restrict__ Al,
                    const __nv_bfloat16* __restrict__ Bh, const __nv_bfloat16* __restrict__ Bl,
                    const float* __restrict__ Bf,
                    float* __restrict__ C, int K, int N,
                    long sA, long sB, long sC)
{
    extern __shared__ __nv_bfloat16 smbuf[];
    const int bz = blockIdx.z;
    Ah += bz * sA;  Al += bz * sA;
    if (MODE == 0) { Bh += bz * sB;  Bl += bz * sB; }
    else           { Bf += bz * sB; }
    C  += bz * sC;

    const int tid   = threadIdx.x;
    const int lane  = tid & 31;
    const int wid   = tid >> 5;
    const int warp_m = wid >> 2;
    const int warp_n = wid & 3;
    const int bn = blockIdx.x * BN;
    const int bm = blockIdx.y * BM;

    const uint32_t su = (uint32_t)__cvta_generic_to_shared(smbuf);

    const int rowA = (lane & 7) + ((lane >> 3) & 1) * 8;
    const int colA = (lane >> 4) * 8;
    const uint32_t aOff = (uint32_t)(((warp_m * 64 + rowA) * APITCH + colA) * 2);
    const int rowB = (lane & 7) + ((lane >> 3) & 1) * 8;
    const int colB = warp_n * 32 + ((lane >> 4) & 1) * 8;
    const uint32_t bOff = (uint32_t)((rowB * BPITCH + colB) * 2);

    float acc[4][4][4];
#pragma unroll
    for (int i = 0; i < 4; i++)
#pragma unroll
        for (int j = 0; j < 4; j++)
#pragma unroll
            for (int r = 0; r < 4; r++) acc[i][j][r] = 0.f;

    float4 breg[4];

#define LOAD_A(buf, kt) do {                                                         \
    _Pragma("unroll")                                                                \
    for (int p = 0; p < 2; p++) {                                                    \
        int id = tid + p * 256;                                                      \
        int ra = id >> 2, ca = (id & 3) * 8;                                         \
        uint32_t dA = su + (uint32_t)(((buf)*BUFE + ra*APITCH + ca) * 2);            \
        CP16(dA + OA_H*2, Ah + (long)(bm + ra) * K + (kt) + ca);                     \
        CP16(dA + OA_L*2, Al + (long)(bm + ra) * K + (kt) + ca);                     \
    }                                                                                \
} while (0)

#define LOAD_B0(buf, kt) do {                                                        \
    _Pragma("unroll")                                                                \
    for (int p = 0; p < 2; p++) {                                                    \
        int id = tid + p * 256;                                                      \
        int rb = id >> 4, cb = (id & 15) * 8;                                        \
        uint32_t dB = su + (uint32_t)(((buf)*BUFE + rb*BPITCH + cb) * 2);            \
        CP16(dB + OB_H*2, Bh + (long)((kt) + rb) * N + bn + cb);                     \
        CP16(dB + OB_L*2, Bl + (long)((kt) + rb) * N + bn + cb);                     \
    }                                                                                \
} while (0)

#define LDG_B(kt) do {                                                               \
    _Pragma("unroll")                                                                \
    for (int p = 0; p < 4; p++) {                                                    \
        int id = tid + p * 256;                                                      \
        int rb = id >> 5, cb = (id & 31) * 4;                                        \
        breg[p] = *(const float4*)(Bf + (long)((kt) + rb) * N + bn + cb);            \
    }                                                                                \
} while (0)

#define CVT_STS_B(buf) do {                                                          \
    _Pragma("unroll")                                                                \
    for (int p = 0; p < 4; p++) {                                                    \
        int id = tid + p * 256;                                                      \
        int rb = id >> 5, cb = (id & 31) * 4;                                        \
        float vv[4] = {breg[p].x, breg[p].y, breg[p].z, breg[p].w};                  \
        __nv_bfloat16 hb4[4], lb4[4];                                                \
        _Pragma("unroll")                                                            \
        for (int j = 0; j < 4; j++) {                                                \
            hb4[j] = __float2bfloat16(vv[j]);                                        \
            lb4[j] = __float2bfloat16(vv[j] - __bfloat162float(hb4[j]));             \
        }                                                                            \
        __nv_bfloat16* bp = smbuf + (buf)*BUFE + rb*BPITCH + cb;                     \
        *(uint2*)(bp + OB_H) = *(uint2*)hb4;                                         \
        *(uint2*)(bp + OB_L) = *(uint2*)lb4;                                         \
    }                                                                                \
} while (0)

    LOAD_A(0, 0);
    if (MODE == 0) LOAD_B0(0, 0);
    CP_COMMIT();
    if (MODE == 1) LDG_B(0);
    CP_WAIT0();
    if (MODE == 1) CVT_STS_B(0);
    __syncthreads();

    int buf = 0;
    for (int kt = BK; kt <= K; kt += BK) {
        if (kt < K) {
            LOAD_A(buf ^ 1, kt);
            if (MODE == 0) LOAD_B0(buf ^ 1, kt);
            CP_COMMIT();
            if (MODE == 1) LDG_B(kt);
        }

        const uint32_t stage = su + (uint32_t)(buf * BUFE * 2);
#pragma unroll
        for (int kk = 0; kk < BK; kk += 16) {
            uint32_t fbh[4][2], fbl[4][2];
#pragma unroll
            for (int pr = 0; pr < 2; pr++) {
                uint32_t adH = stage + (uint32_t)(OB_H*2) + (uint32_t)(kk*BPITCH*2) + bOff + (uint32_t)(pr*32);
                LDSM4T(fbh[2*pr][0], fbh[2*pr][1], fbh[2*pr+1][0], fbh[2*pr+1][1], adH);
                uint32_t adL = stage + (uint32_t)(OB_L*2) + (uint32_t)(kk*BPITCH*2) + bOff + (uint32_t)(pr*32);
                LDSM4T(fbl[2*pr][0], fbl[2*pr][1], fbl[2*pr+1][0], fbl[2*pr+1][1], adL);
            }
#pragma unroll
            for (int mt = 0; mt < 4; mt++) {
                uint32_t fah[4], fal[4];
                uint32_t aaH = stage + (uint32_t)(OA_H*2) + aOff + (uint32_t)((mt*16*APITCH + kk) * 2);
                LDSM4(fah[0], fah[1], fah[2], fah[3], aaH);
                uint32_t aaL = stage + (uint32_t)(OA_L*2) + aOff + (uint32_t)((mt*16*APITCH + kk) * 2);
                LDSM4(fal[0], fal[1], fal[2], fal[3], aaL);
#pragma unroll
                for (int nt = 0; nt < 4; nt++) {
                    MMA3(acc[mt][nt], fah, fbh[nt]);
                    MMA3(acc[mt][nt], fah, fbl[nt]);
                    MMA3(acc[mt][nt], fal, fbh[nt]);
                }
            }
        }

        if (kt < K) {
            CP_WAIT0();
            if (MODE == 1) CVT_STS_B(buf ^ 1);
            __syncthreads();
            buf ^= 1;
        }
    }
#undef LOAD_A
#undef LOAD_B0
#undef LDG_B
#undef CVT_STS_B

    const int r0 = warp_m * 64 + (lane >> 2);
    const int c0 = warp_n * 32 + (lane & 3) * 2;

    if (MODE == 1 && blockIdx.y < 2) {
        // ---- q path: softmax over d, write bf16 hi/lo ----
        __syncthreads();
        float* sf = (float*)smbuf;
#pragma unroll
        for (int mt = 0; mt < 4; mt++)
#pragma unroll
            for (int nt = 0; nt < 4; nt++) {
                int r = r0 + mt * 16, c = c0 + nt * 8;
                sf[r * EPI_PITCH + c]           = acc[mt][nt][0];
                sf[r * EPI_PITCH + c + 1]       = acc[mt][nt][1];
                sf[(r + 8) * EPI_PITCH + c]     = acc[mt][nt][2];
                sf[(r + 8) * EPI_PITCH + c + 1] = acc[mt][nt][3];
            }
        __syncthreads();

        const int col = tid & 127;
        const int h0  = tid >> 7;
        const long n  = bn + col;
#pragma unroll
        for (int hh = h0; hh < 4; hh += 2) {
            float v[DH];
            float mx = -1e30f;
#pragma unroll
            for (int d = 0; d < DH; d++) {
                v[d] = sf[(hh * DH + d) * EPI_PITCH + col];
                mx = fmaxf(mx, v[d]);
            }
            float s = 0.f;
#pragma unroll
            for (int d = 0; d < DH; d++) { v[d] = expf(v[d] - mx); s += v[d]; }
            float inv = 1.f / s;
            const int hglob = blockIdx.y * 4 + hh;
            __nv_bfloat16* qh = g_qh + ((long)bz * CDIM + hglob * DH) * NTOK + n;
            __nv_bfloat16* ql = g_ql + ((long)bz * CDIM + hglob * DH) * NTOK + n;
#pragma unroll
            for (int d = 0; d < DH; d++) {
                float q = v[d] * inv;
                __nv_bfloat16 hb = __float2bfloat16(q);
                qh[(long)d * NTOK] = hb;
                ql[(long)d * NTOK] = __float2bfloat16(q - __bfloat162float(hb));
            }
        }
    } else if (MODE == 1 && blockIdx.y < 4) {
        // ---- k path: exp -> fp16 store + fp32 partial row sums via smem ----
        __syncthreads();
        float* sf = (float*)smbuf;
#pragma unroll
        for (int mt = 0; mt < 4; mt++)
#pragma unroll
            for (int nt = 0; nt < 4; nt++) {
                int r = r0 + mt * 16, c = c0 + nt * 8;
                float e0 = expf(acc[mt][nt][0]);
                float e1 = expf(acc[mt][nt][1]);
                float e2 = expf(acc[mt][nt][2]);
                float e3 = expf(acc[mt][nt][3]);
                long kr = (blockIdx.y - 2) * 128;
                long i01 = ((long)bz * CDIM + kr + r) * NTOK + bn + c;
                *(uint32_t*)(g_ekf + i01)             = pack_half2(e0, e1);
                *(uint32_t*)(g_ekf + i01 + 8L * NTOK) = pack_half2(e2, e3);
                sf[r * EPI_PITCH + c]           = e0;
                sf[r * EPI_PITCH + c + 1]       = e1;
                sf[(r + 8) * EPI_PITCH + c]     = e2;
                sf[(r + 8) * EPI_PITCH + c + 1] = e3;
            }
        __syncthreads();
        if (tid < 128) {
            float s = 0.f;
#pragma unroll 8
            for (int c = 0; c < 128; c++) s += sf[tid * EPI_PITCH + c];
            int kr = (blockIdx.y - 2) * 128 + tid;
            g_ksum_part[((long)bz * 256 + kr) * 256 + blockIdx.x] = s;
        }
    } else if (MODE == 1) {
        // ---- v path: fp16 store ----
#pragma unroll
        for (int mt = 0; mt < 4; mt++)
#pragma unroll
            for (int nt = 0; nt < 4; nt++) {
                int r = r0 + mt * 16, c = c0 + nt * 8;
                long vr = (blockIdx.y - 4) * 128;
                long i01 = ((long)bz * CDIM + vr + r) * NTOK + bn + c;
                *(uint32_t*)(g_vf + i01)             = pack_half2(acc[mt][nt][0], acc[mt][nt][1]);
                *(uint32_t*)(g_vf + i01 + 8L * NTOK) = pack_half2(acc[mt][nt][2], acc[mt][nt][3]);
            }
    } else {
        // ---- plain fp32 store (GEMM3 output) ----
#pragma unroll
        for (int mt = 0; mt < 4; mt++)
#pragma unroll
            for (int nt = 0; nt < 4; nt++) {
                long row = bm + r0 + mt * 16;
                float* cp = C + row * (long)N + bn + c0 + nt * 8;
                *(float2*)cp               = make_float2(acc[mt][nt][0], acc[mt][nt][1]);
                *(float2*)(cp + 8*(long)N) = make_float2(acc[mt][nt][2], acc[mt][nt][3]);
            }
    }
}

// ---------------------------------------------------------------------------
// fp32 -> (bf16 hi, bf16 lo) split conversion (weights only).
// ---------------------------------------------------------------------------
__global__ void cvt_split(const float* __restrict__ src,
                          __nv_bfloat16* __restrict__ h, __nv_bfloat16* __restrict__ l,
                          long n)
{
    long i = ((long)blockIdx.x * blockDim.x + threadIdx.x) * 4;
    if (i >= n) return;
    float4 v = *(const float4*)(src + i);
    float a[4] = {v.x, v.y, v.z, v.w};
#pragma unroll
    for (int j = 0; j < 4; j++) {
        __nv_bfloat16 hh = __float2bfloat16(a[j]);
        h[i + j] = hh;
        l[i + j] = __float2bfloat16(a[j] - __bfloat162float(hh));
    }
}

// ---------------------------------------------------------------------------
// Reduce per-ntile partial k row sums. Deterministic.
// ---------------------------------------------------------------------------
__global__ void ksum_reduce_kernel()
{
    int b  = blockIdx.x >> 8;
    int kr = blockIdx.x & 255;
    __shared__ float red[256];
    red[threadIdx.x] = g_ksum_part[((long)b * 256 + kr) * 256 + threadIdx.x];
    __syncthreads();
    for (int o = 128; o > 0; o >>= 1) {
        if (threadIdx.x < o) red[threadIdx.x] += red[threadIdx.x + o];
        __syncthreads();
    }
    if (threadIdx.x == 0) g_ksum[b * 256 + kr] = red[0];
}

// ---------------------------------------------------------------------------
// Partial contexts via fp16 mma over 128-token stripes.
// ctx[d][e] = sum_n ek[d,n] * v[e,n]; fragments LDG'd directly from global.
// One warp per stripe; single fp16 MMA term (fp32 accumulate).
// ---------------------------------------------------------------------------
__global__ __launch_bounds__(256)
void ctx_part_kernel()
{
    const int w      = threadIdx.x >> 5;
    const int lane   = threadIdx.x & 31;
    const int stripe = blockIdx.x * 8 + w;     // 0..255
    const int h      = blockIdx.y;
    const int b      = blockIdx.z;
    const int lr = lane >> 2, lc = lane & 3;

    const long chbase = ((long)b * CDIM + h * DH) * NTOK;
    const int  n0 = stripe * 128;

    float acc[2][4][4];
#pragma unroll
    for (int i = 0; i < 2; i++)
#pragma unroll
        for (int j = 0; j < 4; j++)
#pragma unroll
            for (int r = 0; r < 4; r++) acc[i][j][r] = 0.f;

#pragma unroll
    for (int c = 0; c < 4; c++) {
#pragma unroll
        for (int ks = 0; ks < 2; ks++) {
            const long tk = n0 + c * 32 + ks * 16 + lc * 2;
            uint32_t fa[2][4], fb[4][2];
#pragma unroll
            for (int mt = 0; mt < 2; mt++) {
                long r0i = chbase + (long)(mt * 16 + lr) * NTOK + tk;
                long r8i = r0i + 8L * NTOK;
                fa[mt][0] = *(const uint32_t*)(g_ekf + r0i);
                fa[mt][1] = *(const uint32_t*)(g_ekf + r8i);
                fa[mt][2] = *(const uint32_t*)(g_ekf + r0i + 8);
                fa[mt][3] = *(const uint32_t*)(g_ekf + r8i + 8);
            }
#pragma unroll
            for (int nt = 0; nt < 4; nt++) {
                long rbi = chbase + (long)(nt * 8 + lr) * NTOK + tk;
                fb[nt][0] = *(const uint32_t*)(g_vf + rbi);
                fb[nt][1] = *(const uint32_t*)(g_vf + rbi + 8);
            }
#pragma unroll
            for (int mt = 0; mt < 2; mt++)
#pragma unroll
                for (int nt = 0; nt < 4; nt++)
                    MMAH(acc[mt][nt], fa[mt], fb[nt]);
        }
    }

    float* out = g_ctx_part + ((long)((b * HEADS + h) * 256) + stripe) * (DH * DH);
#pragma unroll
    for (int mt = 0; mt < 2; mt++)
#pragma unroll
        for (int nt = 0; nt < 4; nt++) {
            int d0 = mt * 16 + lr, e0 = nt * 8 + lc * 2;
            out[d0 * DH + e0]           = acc[mt][nt][0];
            out[d0 * DH + e0 + 1]       = acc[mt][nt][1];
            out[(d0 + 8) * DH + e0]     = acc[mt][nt][2];
            out[(d0 + 8) * DH + e0 + 1] = acc[mt][nt][3];
        }
}

__global__ void ctx_reduce_kernel()
{
    int idx = blockIdx.x * blockDim.x + threadIdx.x;  // < B_*HEADS*1024
    int de = idx % (DH * DH);
    int bh = idx / (DH * DH);
    int d  = de / DH;
    int b  = bh / HEADS, h = bh % HEADS;
    const float* p = g_ctx_part + (long)bh * 256 * (DH * DH) + de;
    float s = 0.f;
#pragma unroll 8
    for (int st = 0; st < 256; st++) s += p[(long)st * (DH * DH)];
    float inv = 1.f / g_ksum[b * 256 + h * DH + d];
    g_ctx[(long)bh * (DH * DH) + de] = s * inv;
}

// ---------------------------------------------------------------------------
// Fold w_out with context; emit bf16 hi/lo W2.
// ---------------------------------------------------------------------------
__global__ void fold_w2_kernel(const float* __restrict__ w_out)
{
    int idx = blockIdx.x * blockDim.x + threadIdx.x;  // < B_*256*256
    int hd = idx % 256;
    int o  = (idx / 256) % 256;
    int b  = idx / 65536;
    int h = hd / DH, d = hd % DH;
    const float* wrow = w_out + o * 256 + h * DH;
    const float* ctx  = g_ctx + ((long)(b * HEADS + h) * DH + d) * DH;
    float s = 0.f;
#pragma unroll
    for (int e = 0; e < DH; e++) s = fmaf(wrow[e], ctx[e], s);
    __nv_bfloat16 hh = __float2bfloat16(s);
    g_w2h[(long)b * 65536 + o * 256 + hd] = hh;
    g_w2l[(long)b * 65536 + o * 256 + hd] = __float2bfloat16(s - __bfloat162float(hh));
}

// ---------------------------------------------------------------------------
// Launch
// ---------------------------------------------------------------------------
extern "C" void kernel_launch(void* const* d_in, const int* in_sizes, int n_in,
                              void* d_out, int out_size)
{
    const float* x     = (const float*)d_in[0];  // [2,256,32768]
    const float* w_qkv = (const float*)d_in[1];  // [768,256]
    const float* w_out = (const float*)d_in[2];  // [256,256]
    float* out = (float*)d_out;                  // [2,256,32768]

    __nv_bfloat16 *qh, *ql, *wh, *wl, *w2h, *w2l;
    cudaGetSymbolAddress((void**)&qh,  g_qh);
    cudaGetSymbolAddress((void**)&ql,  g_ql);
    cudaGetSymbolAddress((void**)&wh,  g_wh);
    cudaGetSymbolAddress((void**)&wl,  g_wl);
    cudaGetSymbolAddress((void**)&w2h, g_w2h);
    cudaGetSymbolAddress((void**)&w2l, g_w2l);

    cudaFuncSetAttribute(gemm_bf16split<1>, cudaFuncAttributeMaxDynamicSharedMemorySize, GEMM_SMEM);
    cudaFuncSetAttribute(gemm_bf16split<0>, cudaFuncAttributeMaxDynamicSharedMemorySize, GEMM_SMEM);

    // 0) bf16 hi/lo split of w_qkv only
    cvt_split<<<(O1*CDIM/4 + 255)/256, 256>>>(w_qkv, wh, wl, (long)O1*CDIM);

    // 1) qkv = w_qkv @ x; fused fp32-B conversion + fused q/k/v epilogues
    gemm_bf16split<1><<<dim3(NTOK/BN, O1/BM, B_), 256, GEMM_SMEM>>>(
        wh, wl, nullptr, nullptr, x, nullptr, CDIM, NTOK,
        0L, (long)CDIM*NTOK, 0L);

    // 2) finish k row sums
    ksum_reduce_kernel<<<B_ * 256, 256>>>();

    // 3) partial contexts (fp16 tensor-core, fragment-direct loads)
    ctx_part_kernel<<<dim3(32, HEADS, B_), 256>>>();

    // 4) reduce + normalize contexts
    ctx_reduce_kernel<<<(B_ * HEADS * DH * DH) / 256, 256>>>();

    // 5) fold output weight with context -> bf16 hi/lo
    fold_w2_kernel<<<(B_ * 256 * 256) / 256, 256>>>(w_out);

    // 6) out = W2 @ q  (bf16-pair B path, plain epilogue)
    gemm_bf16split<0><<<dim3(NTOK/BN, CDIM/BM, B_), 256, GEMM_SMEM>>>(
        w2h, w2l, qh, ql, nullptr, out, CDIM, NTOK,
        (long)CDIM*CDIM, (long)CDIM*NTOK, (long)CDIM*NTOK);
}

// round 14
// speedup vs baseline: 1.1913x; 1.0585x over previous
#include <cuda_runtime.h>
#include <cuda_bf16.h>
#include <cuda_fp16.h>
#include <cstdint>
#include <cstddef>
#include <math.h>

// Problem constants
#define B_    2
#define CDIM  256
#define NTOK  32768          // 32*32*32 tokens
#define HEADS 8
#define DH    32
#define O1    768            // 3 * HEADS * DH

// GEMM tiling
#define BM 128
#define BN 128
#define BK 32
#define APITCH 40            // 32 + 8 bf16 pad  (80B rows -> conflict-free ldmatrix)
#define BPITCH 136           // 128 + 8 bf16 pad (272B rows -> conflict-free ldmatrix.trans)
#define OA_H 0
#define OA_L (BM*APITCH)                 // 5120
#define OB_H (2*BM*APITCH)               // 10240
#define OB_L (2*BM*APITCH + BK*BPITCH)   // 14592
#define BUFE (2*BM*APITCH + 2*BK*BPITCH) // 18944 bf16 elems per stage
#define GEMM_SMEM (2*BUFE*2)             // bytes (double buffered) = 75776
#define EPI_PITCH 129                    // fp32 epilogue scratch pitch

// ---------------------------------------------------------------------------
// Scratch (device globals; no cudaMalloc allowed)
// ---------------------------------------------------------------------------
__device__ float g_ksum[B_ * 256];
__device__ float g_ksum_part[B_ * 256 * 256];                    // [b][krow][ntile]
__device__ float g_ctx_part[(size_t)B_ * HEADS * 256 * DH * DH];
__device__ float g_ctx[B_ * HEADS * DH * DH];
__device__ __align__(16) __half g_ekf[(size_t)B_*CDIM*NTOK];     // exp(k) fp16
__device__ __align__(16) __half g_vf [(size_t)B_*CDIM*NTOK];     // v fp16
__device__ __align__(16) __half g_qf [(size_t)B_*CDIM*NTOK];     // q fp16 (single)
__device__ __align__(16) __nv_bfloat16 g_wh[O1*CDIM];
__device__ __align__(16) __nv_bfloat16 g_wl[O1*CDIM];
__device__ __align__(16) __half g_w2h[B_*CDIM*CDIM];             // W2 fp16 hi
__device__ __align__(16) __half g_w2l[B_*CDIM*CDIM];             // W2 fp16 lo

// ---------------------------------------------------------------------------
// PTX helpers
// ---------------------------------------------------------------------------
#define CP16(dst, src) \
    asm volatile("cp.async.cg.shared.global [%0], [%1], 16;" :: "r"(dst), "l"(src) : "memory")
#define CP_COMMIT() asm volatile("cp.async.commit_group;" ::: "memory")
#define CP_WAIT0()  asm volatile("cp.async.wait_group 0;"  ::: "memory")

#define LDSM4(r0,r1,r2,r3,a) \
    asm volatile("ldmatrix.sync.aligned.m8n8.x4.shared.b16 {%0,%1,%2,%3}, [%4];" \
                 : "=r"(r0),"=r"(r1),"=r"(r2),"=r"(r3) : "r"(a))
#define LDSM4T(r0,r1,r2,r3,a) \
    asm volatile("ldmatrix.sync.aligned.m8n8.x4.trans.shared.b16 {%0,%1,%2,%3}, [%4];" \
                 : "=r"(r0),"=r"(r1),"=r"(r2),"=r"(r3) : "r"(a))

#define MMA3(d, a, b) \
    asm volatile("mma.sync.aligned.m16n8k16.row.col.f32.bf16.bf16.f32 " \
                 "{%0,%1,%2,%3},{%4,%5,%6,%7},{%8,%9},{%0,%1,%2,%3};" \
                 : "+f"((d)[0]),"+f"((d)[1]),"+f"((d)[2]),"+f"((d)[3]) \
                 : "r"((a)[0]),"r"((a)[1]),"r"((a)[2]),"r"((a)[3]), \
                   "r"((b)[0]),"r"((b)[1]))

#define MMAH(d, a, b) \
    asm volatile("mma.sync.aligned.m16n8k16.row.col.f32.f16.f16.f32 " \
                 "{%0,%1,%2,%3},{%4,%5,%6,%7},{%8,%9},{%0,%1,%2,%3};" \
                 : "+f"((d)[0]),"+f"((d)[1]),"+f"((d)[2]),"+f"((d)[3]) \
                 : "r"((a)[0]),"r"((a)[1]),"r"((a)[2]),"r"((a)[3]), \
                   "r"((b)[0]),"r"((b)[1]))

__device__ __forceinline__ uint32_t pack_half2(float a, float b)
{
    __half2 p = __floats2half2_rn(a, b);
    return *(uint32_t*)&p;
}

// ---------------------------------------------------------------------------
// Tensor-core GEMM, two modes.
// MODE 1 (GEMM1): 3-term split bf16 (ah*bh + ah*bl + al*bh). A = w_qkv bf16
//   pair; B = x fp32, converted to bf16 hi/lo in-kernel. Fused epilogues:
//   blockIdx.y 0-1 q-softmax -> g_qf fp16; 2-3 exp(k) -> g_ekf fp16 + fp32
//   row sums; 4-5 v -> g_vf fp16.
// MODE 0 (GEMM3): 2-term fp16 (w2h*q + w2l*q). A = W2 fp16 pair; B = q fp16
//   single plane. Plain fp32 epilogue -> C. (q repr error ~2^-12; random-walk
//   denominator keeps rel_err at ulp level — validated R13.)
// ---------------------------------------------------------------------------
template <int MODE>
__global__ __launch_bounds__(256, 2)
void gemm_tc(const __nv_bfloat16* __restrict__ Ah, const __nv_bfloat16* __restrict__ Al,
             const __nv_bfloat16* __restrict__ Bh,
             const float* __restrict__ Bf,
             float* __restrict__ C, int K, int N,
             long sA, long sB, long sC)
{
    extern __shared__ __nv_bfloat16 smbuf[];
    const int bz = blockIdx.z;
    Ah += bz * sA;  Al += bz * sA;
    if (MODE == 0) Bh += bz * sB;
    else           Bf += bz * sB;
    C  += bz * sC;

    const int tid   = threadIdx.x;
    const int lane  = tid & 31;
    const int wid   = tid >> 5;
    const int warp_m = wid >> 2;
    const int warp_n = wid & 3;
    const int bn = blockIdx.x * BN;
    const int bm = blockIdx.y * BM;

    const uint32_t su = (uint32_t)__cvta_generic_to_shared(smbuf);

    const int rowA = (lane & 7) + ((lane >> 3) & 1) * 8;
    const int colA = (lane >> 4) * 8;
    const uint32_t aOff = (uint32_t)(((warp_m * 64 + rowA) * APITCH + colA) * 2);
    const int rowB = (lane & 7) + ((lane >> 3) & 1) * 8;
    const int colB = warp_n * 32 + ((lane >> 4) & 1) * 8;
    const uint32_t bOff = (uint32_t)((rowB * BPITCH + colB) * 2);

    float acc[4][4][4];
#pragma unroll
    for (int i = 0; i < 4; i++)
#pragma unroll
        for (int j = 0; j < 4; j++)
#pragma unroll
            for (int r = 0; r < 4; r++) acc[i][j][r] = 0.f;

    float4 breg[4];

#define LOAD_A(buf, kt) do {                                                         \
    _Pragma("unroll")                                                                \
    for (int p = 0; p < 2; p++) {                                                    \
        int id = tid + p * 256;                                                      \
        int ra = id >> 2, ca = (id & 3) * 8;                                         \
        uint32_t dA = su + (uint32_t)(((buf)*BUFE + ra*APITCH + ca) * 2);            \
        CP16(dA + OA_H*2, Ah + (long)(bm + ra) * K + (kt) + ca);                     \
        CP16(dA + OA_L*2, Al + (long)(bm + ra) * K + (kt) + ca);                     \
    }                                                                                \
} while (0)

    // MODE 0: single bf16/fp16 B plane (q)
#define LOAD_B0(buf, kt) do {                                                        \
    _Pragma("unroll")                                                                \
    for (int p = 0; p < 2; p++) {                                                    \
        int id = tid + p * 256;                                                      \
        int rb = id >> 4, cb = (id & 15) * 8;                                        \
        uint32_t dB = su + (uint32_t)(((buf)*BUFE + rb*BPITCH + cb) * 2);            \
        CP16(dB + OB_H*2, Bh + (long)((kt) + rb) * N + bn + cb);                     \
    }                                                                                \
} while (0)

#define LDG_B(kt) do {                                                               \
    _Pragma("unroll")                                                                \
    for (int p = 0; p < 4; p++) {                                                    \
        int id = tid + p * 256;                                                      \
        int rb = id >> 5, cb = (id & 31) * 4;                                        \
        breg[p] = *(const float4*)(Bf + (long)((kt) + rb) * N + bn + cb);            \
    }                                                                                \
} while (0)

#define CVT_STS_B(buf) do {                                                          \
    _Pragma("unroll")                                                                \
    for (int p = 0; p < 4; p++) {                                                    \
        int id = tid + p * 256;                                                      \
        int rb = id >> 5, cb = (id & 31) * 4;                                        \
        float vv[4] = {breg[p].x, breg[p].y, breg[p].z, breg[p].w};                  \
        __nv_bfloat16 hb4[4], lb4[4];                                                \
        _Pragma("unroll")                                                            \
        for (int j = 0; j < 4; j++) {                                                \
            hb4[j] = __float2bfloat16(vv[j]);                                        \
            lb4[j] = __float2bfloat16(vv[j] - __bfloat162float(hb4[j]));             \
        }                                                                            \
        __nv_bfloat16* bp = smbuf + (buf)*BUFE + rb*BPITCH + cb;                     \
        *(uint2*)(bp + OB_H) = *(uint2*)hb4;                                         \
        *(uint2*)(bp + OB_L) = *(uint2*)lb4;                                         \
    }                                                                                \
} while (0)

    LOAD_A(0, 0);
    if (MODE == 0) LOAD_B0(0, 0);
    CP_COMMIT();
    if (MODE == 1) LDG_B(0);
    CP_WAIT0();
    if (MODE == 1) CVT_STS_B(0);
    __syncthreads();

    int buf = 0;
    for (int kt = BK; kt <= K; kt += BK) {
        if (kt < K) {
            LOAD_A(buf ^ 1, kt);
            if (MODE == 0) LOAD_B0(buf ^ 1, kt);
            CP_COMMIT();
            if (MODE == 1) LDG_B(kt);
        }

        const uint32_t stage = su + (uint32_t)(buf * BUFE * 2);
#pragma unroll
        for (int kk = 0; kk < BK; kk += 16) {
            uint32_t fbh[4][2], fbl[4][2];
#pragma unroll
            for (int pr = 0; pr < 2; pr++) {
                uint32_t adH = stage + (uint32_t)(OB_H*2) + (uint32_t)(kk*BPITCH*2) + bOff + (uint32_t)(pr*32);
                LDSM4T(fbh[2*pr][0], fbh[2*pr][1], fbh[2*pr+1][0], fbh[2*pr+1][1], adH);
                if (MODE == 1) {
                    uint32_t adL = stage + (uint32_t)(OB_L*2) + (uint32_t)(kk*BPITCH*2) + bOff + (uint32_t)(pr*32);
                    LDSM4T(fbl[2*pr][0], fbl[2*pr][1], fbl[2*pr+1][0], fbl[2*pr+1][1], adL);
                }
            }
#pragma unroll
            for (int mt = 0; mt < 4; mt++) {
                uint32_t fah[4], fal[4];
                uint32_t aaH = stage + (uint32_t)(OA_H*2) + aOff + (uint32_t)((mt*16*APITCH + kk) * 2);
                LDSM4(fah[0], fah[1], fah[2], fah[3], aaH);
                uint32_t aaL = stage + (uint32_t)(OA_L*2) + aOff + (uint32_t)((mt*16*APITCH + kk) * 2);
                LDSM4(fal[0], fal[1], fal[2], fal[3], aaL);
                if (MODE == 1) {
#pragma unroll
                    for (int nt = 0; nt < 4; nt++) {
                        MMA3(acc[mt][nt], fah, fbh[nt]);
                        MMA3(acc[mt][nt], fah, fbl[nt]);
                        MMA3(acc[mt][nt], fal, fbh[nt]);
                    }
                } else {
#pragma unroll
                    for (int nt = 0; nt < 4; nt++) MMAH(acc[mt][nt], fah, fbh[nt]);
#pragma unroll
                    for (int nt = 0; nt < 4; nt++) MMAH(acc[mt][nt], fal, fbh[nt]);
                }
            }
        }

        if (kt < K) {
            CP_WAIT0();
            if (MODE == 1) CVT_STS_B(buf ^ 1);
            __syncthreads();
            buf ^= 1;
        }
    }
#undef LOAD_A
#undef LOAD_B0
#undef LDG_B
#undef CVT_STS_B

    const int r0 = warp_m * 64 + (lane >> 2);
    const int c0 = warp_n * 32 + (lane & 3) * 2;

    if (MODE == 1 && blockIdx.y < 2) {
        // ---- q path: softmax over d, write fp16 (single) ----
        __syncthreads();
        float* sf = (float*)smbuf;
#pragma unroll
        for (int mt = 0; mt < 4; mt++)
#pragma unroll
            for (int nt = 0; nt < 4; nt++) {
                int r = r0 + mt * 16, c = c0 + nt * 8;
                sf[r * EPI_PITCH + c]           = acc[mt][nt][0];
                sf[r * EPI_PITCH + c + 1]       = acc[mt][nt][1];
                sf[(r + 8) * EPI_PITCH + c]     = acc[mt][nt][2];
                sf[(r + 8) * EPI_PITCH + c + 1] = acc[mt][nt][3];
            }
        __syncthreads();

        const int col = tid & 127;
        const int h0  = tid >> 7;
        const long n  = bn + col;
#pragma unroll
        for (int hh = h0; hh < 4; hh += 2) {
            float v[DH];
            float mx = -1e30f;
#pragma unroll
            for (int d = 0; d < DH; d++) {
                v[d] = sf[(hh * DH + d) * EPI_PITCH + col];
                mx = fmaxf(mx, v[d]);
            }
            float s = 0.f;
#pragma unroll
            for (int d = 0; d < DH; d++) { v[d] = expf(v[d] - mx); s += v[d]; }
            float inv = 1.f / s;
            const int hglob = blockIdx.y * 4 + hh;
            __half* qp = g_qf + ((long)bz * CDIM + hglob * DH) * NTOK + n;
#pragma unroll
            for (int d = 0; d < DH; d++)
                qp[(long)d * NTOK] = __float2half(v[d] * inv);
        }
    } else if (MODE == 1 && blockIdx.y < 4) {
        // ---- k path: exp -> fp16 store + fp32 partial row sums via smem ----
        __syncthreads();
        float* sf = (float*)smbuf;
#pragma unroll
        for (int mt = 0; mt < 4; mt++)
#pragma unroll
            for (int nt = 0; nt < 4; nt++) {
                int r = r0 + mt * 16, c = c0 + nt * 8;
                float e0 = expf(acc[mt][nt][0]);
                float e1 = expf(acc[mt][nt][1]);
                float e2 = expf(acc[mt][nt][2]);
                float e3 = expf(acc[mt][nt][3]);
                long kr = (blockIdx.y - 2) * 128;
                long i01 = ((long)bz * CDIM + kr + r) * NTOK + bn + c;
                *(uint32_t*)(g_ekf + i01)             = pack_half2(e0, e1);
                *(uint32_t*)(g_ekf + i01 + 8L * NTOK) = pack_half2(e2, e3);
                sf[r * EPI_PITCH + c]           = e0;
                sf[r * EPI_PITCH + c + 1]       = e1;
                sf[(r + 8) * EPI_PITCH + c]     = e2;
                sf[(r + 8) * EPI_PITCH + c + 1] = e3;
            }
        __syncthreads();
        if (tid < 128) {
            float s = 0.f;
#pragma unroll 8
            for (int c = 0; c < 128; c++) s += sf[tid * EPI_PITCH + c];
            int kr = (blockIdx.y - 2) * 128 + tid;
            g_ksum_part[((long)bz * 256 + kr) * 256 + blockIdx.x] = s;
        }
    } else if (MODE == 1) {
        // ---- v path: fp16 store ----
#pragma unroll
        for (int mt = 0; mt < 4; mt++)
#pragma unroll
            for (int nt = 0; nt < 4; nt++) {
                int r = r0 + mt * 16, c = c0 + nt * 8;
                long vr = (blockIdx.y - 4) * 128;
                long i01 = ((long)bz * CDIM + vr + r) * NTOK + bn + c;
                *(uint32_t*)(g_vf + i01)             = pack_half2(acc[mt][nt][0], acc[mt][nt][1]);
                *(uint32_t*)(g_vf + i01 + 8L * NTOK) = pack_half2(acc[mt][nt][2], acc[mt][nt][3]);
            }
    } else {
        // ---- plain fp32 store (GEMM3 output) ----
#pragma unroll
        for (int mt = 0; mt < 4; mt++)
#pragma unroll
            for (int nt = 0; nt < 4; nt++) {
                long row = bm + r0 + mt * 16;
                float* cp = C + row * (long)N + bn + c0 + nt * 8;
                *(float2*)cp               = make_float2(acc[mt][nt][0], acc[mt][nt][1]);
                *(float2*)(cp + 8*(long)N) = make_float2(acc[mt][nt][2], acc[mt][nt][3]);
            }
    }
}

// ---------------------------------------------------------------------------
// fp32 -> (bf16 hi, bf16 lo) split conversion (w_qkv only).
// ---------------------------------------------------------------------------
__global__ void cvt_split(const float* __restrict__ src,
                          __nv_bfloat16* __restrict__ h, __nv_bfloat16* __restrict__ l,
                          long n)
{
    long i = ((long)blockIdx.x * blockDim.x + threadIdx.x) * 4;
    if (i >= n) return;
    float4 v = *(const float4*)(src + i);
    float a[4] = {v.x, v.y, v.z, v.w};
#pragma unroll
    for (int j = 0; j < 4; j++) {
        __nv_bfloat16 hh = __float2bfloat16(a[j]);
        h[i + j] = hh;
        l[i + j] = __float2bfloat16(a[j] - __bfloat162float(hh));
    }
}

// ---------------------------------------------------------------------------
// Reduce per-ntile partial k row sums. Deterministic.
// ---------------------------------------------------------------------------
__global__ void ksum_reduce_kernel()
{
    int b  = blockIdx.x >> 8;
    int kr = blockIdx.x & 255;
    __shared__ float red[256];
    red[threadIdx.x] = g_ksum_part[((long)b * 256 + kr) * 256 + threadIdx.x];
    __syncthreads();
    for (int o = 128; o > 0; o >>= 1) {
        if (threadIdx.x < o) red[threadIdx.x] += red[threadIdx.x + o];
        __syncthreads();
    }
    if (threadIdx.x == 0) g_ksum[b * 256 + kr] = red[0];
}

// ---------------------------------------------------------------------------
// Partial contexts via fp16 mma over 128-token stripes.
// ---------------------------------------------------------------------------
__global__ __launch_bounds__(256)
void ctx_part_kernel()
{
    const int w      = threadIdx.x >> 5;
    const int lane   = threadIdx.x & 31;
    const int stripe = blockIdx.x * 8 + w;     // 0..255
    const int h      = blockIdx.y;
    const int b      = blockIdx.z;
    const int lr = lane >> 2, lc = lane & 3;

    const long chbase = ((long)b * CDIM + h * DH) * NTOK;
    const int  n0 = stripe * 128;

    float acc[2][4][4];
#pragma unroll
    for (int i = 0; i < 2; i++)
#pragma unroll
        for (int j = 0; j < 4; j++)
#pragma unroll
            for (int r = 0; r < 4; r++) acc[i][j][r] = 0.f;

#pragma unroll
    for (int c = 0; c < 4; c++) {
#pragma unroll
        for (int ks = 0; ks < 2; ks++) {
            const long tk = n0 + c * 32 + ks * 16 + lc * 2;
            uint32_t fa[2][4], fb[4][2];
#pragma unroll
            for (int mt = 0; mt < 2; mt++) {
                long r0i = chbase + (long)(mt * 16 + lr) * NTOK + tk;
                long r8i = r0i + 8L * NTOK;
                fa[mt][0] = *(const uint32_t*)(g_ekf + r0i);
                fa[mt][1] = *(const uint32_t*)(g_ekf + r8i);
                fa[mt][2] = *(const uint32_t*)(g_ekf + r0i + 8);
                fa[mt][3] = *(const uint32_t*)(g_ekf + r8i + 8);
            }
#pragma unroll
            for (int nt = 0; nt < 4; nt++) {
                long rbi = chbase + (long)(nt * 8 + lr) * NTOK + tk;
                fb[nt][0] = *(const uint32_t*)(g_vf + rbi);
                fb[nt][1] = *(const uint32_t*)(g_vf + rbi + 8);
            }
#pragma unroll
            for (int mt = 0; mt < 2; mt++)
#pragma unroll
                for (int nt = 0; nt < 4; nt++)
                    MMAH(acc[mt][nt], fa[mt], fb[nt]);
        }
    }

    float* out = g_ctx_part + ((long)((b * HEADS + h) * 256) + stripe) * (DH * DH);
#pragma unroll
    for (int mt = 0; mt < 2; mt++)
#pragma unroll
        for (int nt = 0; nt < 4; nt++) {
            int d0 = mt * 16 + lr, e0 = nt * 8 + lc * 2;
            out[d0 * DH + e0]           = acc[mt][nt][0];
            out[d0 * DH + e0 + 1]       = acc[mt][nt][1];
            out[(d0 + 8) * DH + e0]     = acc[mt][nt][2];
            out[(d0 + 8) * DH + e0 + 1] = acc[mt][nt][3];
        }
}

__global__ void ctx_reduce_kernel()
{
    int idx = blockIdx.x * blockDim.x + threadIdx.x;  // < B_*HEADS*1024
    int de = idx % (DH * DH);
    int bh = idx / (DH * DH);
    int d  = de / DH;
    int b  = bh / HEADS, h = bh % HEADS;
    const float* p = g_ctx_part + (long)bh * 256 * (DH * DH) + de;
    float s = 0.f;
#pragma unroll 8
    for (int st = 0; st < 256; st++) s += p[(long)st * (DH * DH)];
    float inv = 1.f / g_ksum[b * 256 + h * DH + d];
    g_ctx[(long)bh * (DH * DH) + de] = s * inv;
}

// ---------------------------------------------------------------------------
// Fold w_out with context; emit fp16 hi/lo W2.
// ---------------------------------------------------------------------------
__global__ void fold_w2_kernel(const float* __restrict__ w_out)
{
    int idx = blockIdx.x * blockDim.x + threadIdx.x;  // < B_*256*256
    int hd = idx % 256;
    int o  = (idx / 256) % 256;
    int b  = idx / 65536;
    int h = hd / DH, d = hd % DH;
    const float* wrow = w_out + o * 256 + h * DH;
    const float* ctx  = g_ctx + ((long)(b * HEADS + h) * DH + d) * DH;
    float s = 0.f;
#pragma unroll
    for (int e = 0; e < DH; e++) s = fmaf(wrow[e], ctx[e], s);
    __half hh = __float2half(s);
    g_w2h[(long)b * 65536 + o * 256 + hd] = hh;
    g_w2l[(long)b * 65536 + o * 256 + hd] = __float2half(s - __half2float(hh));
}

// ---------------------------------------------------------------------------
// Launch
// ---------------------------------------------------------------------------
extern "C" void kernel_launch(void* const* d_in, const int* in_sizes, int n_in,
                              void* d_out, int out_size)
{
    const float* x     = (const float*)d_in[0];  // [2,256,32768]
    const float* w_qkv = (const float*)d_in[1];  // [768,256]
    const float* w_out = (const float*)d_in[2];  // [256,256]
    float* out = (float*)d_out;                  // [2,256,32768]

    __nv_bfloat16 *wh, *wl;
    __half *qf, *w2h, *w2l;
    cudaGetSymbolAddress((void**)&wh,  g_wh);
    cudaGetSymbolAddress((void**)&wl,  g_wl);
    cudaGetSymbolAddress((void**)&qf,  g_qf);
    cudaGetSymbolAddress((void**)&w2h, g_w2h);
    cudaGetSymbolAddress((void**)&w2l, g_w2l);

    cudaFuncSetAttribute(gemm_tc<1>, cudaFuncAttributeMaxDynamicSharedMemorySize, GEMM_SMEM);
    cudaFuncSetAttribute(gemm_tc<0>, cudaFuncAttributeMaxDynamicSharedMemorySize, GEMM_SMEM);

    // 0) bf16 hi/lo split of w_qkv only
    cvt_split<<<(O1*CDIM/4 + 255)/256, 256>>>(w_qkv, wh, wl, (long)O1*CDIM);

    // 1) qkv = w_qkv @ x; fused fp32-B conversion + fused q/k/v epilogues
    gemm_tc<1><<<dim3(NTOK/BN, O1/BM, B_), 256, GEMM_SMEM>>>(
        wh, wl, nullptr, x, nullptr, CDIM, NTOK,
        0L, (long)CDIM*NTOK, 0L);

    // 2) finish k row sums
    ksum_reduce_kernel<<<B_ * 256, 256>>>();

    // 3) partial contexts (fp16 tensor-core, fragment-direct loads)
    ctx_part_kernel<<<dim3(32, HEADS, B_), 256>>>();

    // 4) reduce + normalize contexts
    ctx_reduce_kernel<<<(B_ * HEADS * DH * DH) / 256, 256>>>();

    // 5) fold output weight with context -> fp16 hi/lo W2
    fold_w2_kernel<<<(B_ * 256 * 256) / 256, 256>>>(w_out);

    // 6) out = W2 @ q  (2-term fp16: A = W2 pair, B = q single)
    gemm_tc<0><<<dim3(NTOK/BN, CDIM/BM, B_), 256, GEMM_SMEM>>>(
        (const __nv_bfloat16*)w2h, (const __nv_bfloat16*)w2l,
        (const __nv_bfloat16*)qf, nullptr, out, CDIM, NTOK,
        (long)CDIM*CDIM, (long)CDIM*NTOK, (long)CDIM*NTOK);
}

// round 15
// speedup vs baseline: 1.4630x; 1.2281x over previous
#include <cuda_runtime.h>
#include <cuda_bf16.h>
#include <cuda_fp16.h>
#include <cstdint>
#include <cstddef>
#include <math.h>

// Problem constants
#define B_    2
#define CDIM  256
#define NTOK  32768          // 32*32*32 tokens
#define HEADS 8
#define DH    32
#define O1    768            // 3 * HEADS * DH

// GEMM tiling
#define BM 128
#define BN 128
#define BK 32
#define APITCH 40            // 32 + 8 fp16 pad  (80B rows -> conflict-free ldmatrix)
#define BPITCH 136           // 128 + 8 fp16 pad (272B rows -> conflict-free ldmatrix.trans)
#define OA_H 0
#define OA_L (BM*APITCH)                 // 5120
#define OB_H (2*BM*APITCH)               // 10240
#define BUFE (2*BM*APITCH + BK*BPITCH)   // 14592 fp16 elems per stage
#define GEMM_SMEM (2*BUFE*2 + 37376)     // keep >= 129*128*4 for fp32 epilogue scratch
#define EPI_PITCH 129                    // fp32 epilogue scratch pitch

// ---------------------------------------------------------------------------
// Scratch (device globals; no cudaMalloc allowed)
// ---------------------------------------------------------------------------
__device__ float g_ksum[B_ * 256];
__device__ float g_ksum_part[B_ * 256 * 256];                    // [b][krow][ntile]
__device__ float g_ctx_part[(size_t)B_ * HEADS * 256 * DH * DH];
__device__ float g_ctx[B_ * HEADS * DH * DH];
__device__ __align__(16) __half g_ekf[(size_t)B_*CDIM*NTOK];     // exp(k) fp16
__device__ __align__(16) __half g_vf [(size_t)B_*CDIM*NTOK];     // v fp16
__device__ __align__(16) __half g_qf [(size_t)B_*CDIM*NTOK];     // q fp16
__device__ __align__(16) __half g_wh[O1*CDIM];                   // w_qkv fp16 hi
__device__ __align__(16) __half g_wl[O1*CDIM];                   // w_qkv fp16 lo
__device__ __align__(16) __half g_w2[B_*CDIM*CDIM];              // W2 fp16 (single)

// ---------------------------------------------------------------------------
// PTX helpers
// ---------------------------------------------------------------------------
#define CP16(dst, src) \
    asm volatile("cp.async.cg.shared.global [%0], [%1], 16;" :: "r"(dst), "l"(src) : "memory")
#define CP_COMMIT() asm volatile("cp.async.commit_group;" ::: "memory")
#define CP_WAIT0()  asm volatile("cp.async.wait_group 0;"  ::: "memory")

#define LDSM4(r0,r1,r2,r3,a) \
    asm volatile("ldmatrix.sync.aligned.m8n8.x4.shared.b16 {%0,%1,%2,%3}, [%4];" \
                 : "=r"(r0),"=r"(r1),"=r"(r2),"=r"(r3) : "r"(a))
#define LDSM4T(r0,r1,r2,r3,a) \
    asm volatile("ldmatrix.sync.aligned.m8n8.x4.trans.shared.b16 {%0,%1,%2,%3}, [%4];" \
                 : "=r"(r0),"=r"(r1),"=r"(r2),"=r"(r3) : "r"(a))

#define MMAH(d, a, b) \
    asm volatile("mma.sync.aligned.m16n8k16.row.col.f32.f16.f16.f32 " \
                 "{%0,%1,%2,%3},{%4,%5,%6,%7},{%8,%9},{%0,%1,%2,%3};" \
                 : "+f"((d)[0]),"+f"((d)[1]),"+f"((d)[2]),"+f"((d)[3]) \
                 : "r"((a)[0]),"r"((a)[1]),"r"((a)[2]),"r"((a)[3]), \
                   "r"((b)[0]),"r"((b)[1]))

__device__ __forceinline__ uint32_t pack_half2(float a, float b)
{
    __half2 p = __floats2half2_rn(a, b);
    return *(uint32_t*)&p;
}

// ---------------------------------------------------------------------------
// fp16 tensor-core GEMM, two modes.
// MODE 1 (GEMM1): 2-term (ah*b + al*b). A = w_qkv fp16 hi/lo pair; B = x fp32
//   converted to single fp16 in-kernel. Fused epilogues: blockIdx.y 0-1
//   q-softmax -> g_qf; 2-3 exp(k) -> g_ekf + fp32 row sums; 4-5 v -> g_vf.
// MODE 0 (GEMM3): 1-term (w2*q). A = W2 fp16 single; B = q fp16 single.
//   Plain fp32 epilogue -> C.
// Error model (R13/R14-validated): input quantization at ulp u costs ~0.7u
// relative on the dot product (random-walk denominator, no cancellation).
// ---------------------------------------------------------------------------
template <int MODE>
__global__ __launch_bounds__(256, 2)
void gemm_tc(const __half* __restrict__ Ah, const __half* __restrict__ Al,
             const __half* __restrict__ Bh,
             const float* __restrict__ Bf,
             float* __restrict__ C, int K, int N,
             long sA, long sB, long sC)
{
    extern __shared__ __half smbuf[];
    const int bz = blockIdx.z;
    Ah += bz * sA;
    if (MODE == 1) Al += bz * sA;
    if (MODE == 0) Bh += bz * sB;
    else           Bf += bz * sB;
    C  += bz * sC;

    const int tid   = threadIdx.x;
    const int lane  = tid & 31;
    const int wid   = tid >> 5;
    const int warp_m = wid >> 2;
    const int warp_n = wid & 3;
    const int bn = blockIdx.x * BN;
    const int bm = blockIdx.y * BM;

    const uint32_t su = (uint32_t)__cvta_generic_to_shared(smbuf);

    const int rowA = (lane & 7) + ((lane >> 3) & 1) * 8;
    const int colA = (lane >> 4) * 8;
    const uint32_t aOff = (uint32_t)(((warp_m * 64 + rowA) * APITCH + colA) * 2);
    const int rowB = (lane & 7) + ((lane >> 3) & 1) * 8;
    const int colB = warp_n * 32 + ((lane >> 4) & 1) * 8;
    const uint32_t bOff = (uint32_t)((rowB * BPITCH + colB) * 2);

    float acc[4][4][4];
#pragma unroll
    for (int i = 0; i < 4; i++)
#pragma unroll
        for (int j = 0; j < 4; j++)
#pragma unroll
            for (int r = 0; r < 4; r++) acc[i][j][r] = 0.f;

    float4 breg[4];

#define LOAD_A(buf, kt) do {                                                         \
    _Pragma("unroll")                                                                \
    for (int p = 0; p < 2; p++) {                                                    \
        int id = tid + p * 256;                                                      \
        int ra = id >> 2, ca = (id & 3) * 8;                                         \
        uint32_t dA = su + (uint32_t)(((buf)*BUFE + ra*APITCH + ca) * 2);            \
        CP16(dA + OA_H*2, Ah + (long)(bm + ra) * K + (kt) + ca);                     \
        if (MODE == 1) CP16(dA + OA_L*2, Al + (long)(bm + ra) * K + (kt) + ca);      \
    }                                                                                \
} while (0)

    // MODE 0: single fp16 B plane (q) via cp.async
#define LOAD_B0(buf, kt) do {                                                        \
    _Pragma("unroll")                                                                \
    for (int p = 0; p < 2; p++) {                                                    \
        int id = tid + p * 256;                                                      \
        int rb = id >> 4, cb = (id & 15) * 8;                                        \
        uint32_t dB = su + (uint32_t)(((buf)*BUFE + rb*BPITCH + cb) * 2);            \
        CP16(dB + OB_H*2, Bh + (long)((kt) + rb) * N + bn + cb);                     \
    }                                                                                \
} while (0)

#define LDG_B(kt) do {                                                               \
    _Pragma("unroll")                                                                \
    for (int p = 0; p < 4; p++) {                                                    \
        int id = tid + p * 256;                                                      \
        int rb = id >> 5, cb = (id & 31) * 4;                                        \
        breg[p] = *(const float4*)(Bf + (long)((kt) + rb) * N + bn + cb);            \
    }                                                                                \
} while (0)

    // MODE 1: convert fp32 x -> single fp16 plane in smem
#define CVT_STS_B(buf) do {                                                          \
    _Pragma("unroll")                                                                \
    for (int p = 0; p < 4; p++) {                                                    \
        int id = tid + p * 256;                                                      \
        int rb = id >> 5, cb = (id & 31) * 4;                                        \
        uint32_t lohi[2];                                                            \
        lohi[0] = pack_half2(breg[p].x, breg[p].y);                                  \
        lohi[1] = pack_half2(breg[p].z, breg[p].w);                                  \
        __half* bp = smbuf + (buf)*BUFE + rb*BPITCH + cb;                            \
        *(uint2*)(bp + OB_H) = *(uint2*)lohi;                                        \
    }                                                                                \
} while (0)

    LOAD_A(0, 0);
    if (MODE == 0) LOAD_B0(0, 0);
    CP_COMMIT();
    if (MODE == 1) LDG_B(0);
    CP_WAIT0();
    if (MODE == 1) CVT_STS_B(0);
    __syncthreads();

    int buf = 0;
    for (int kt = BK; kt <= K; kt += BK) {
        if (kt < K) {
            LOAD_A(buf ^ 1, kt);
            if (MODE == 0) LOAD_B0(buf ^ 1, kt);
            CP_COMMIT();
            if (MODE == 1) LDG_B(kt);
        }

        const uint32_t stage = su + (uint32_t)(buf * BUFE * 2);
#pragma unroll
        for (int kk = 0; kk < BK; kk += 16) {
            uint32_t fb[4][2];
#pragma unroll
            for (int pr = 0; pr < 2; pr++) {
                uint32_t adH = stage + (uint32_t)(OB_H*2) + (uint32_t)(kk*BPITCH*2) + bOff + (uint32_t)(pr*32);
                LDSM4T(fb[2*pr][0], fb[2*pr][1], fb[2*pr+1][0], fb[2*pr+1][1], adH);
            }
#pragma unroll
            for (int mt = 0; mt < 4; mt++) {
                uint32_t fah[4], fal[4];
                uint32_t aaH = stage + (uint32_t)(OA_H*2) + aOff + (uint32_t)((mt*16*APITCH + kk) * 2);
                LDSM4(fah[0], fah[1], fah[2], fah[3], aaH);
                if (MODE == 1) {
                    uint32_t aaL = stage + (uint32_t)(OA_L*2) + aOff + (uint32_t)((mt*16*APITCH + kk) * 2);
                    LDSM4(fal[0], fal[1], fal[2], fal[3], aaL);
#pragma unroll
                    for (int nt = 0; nt < 4; nt++) MMAH(acc[mt][nt], fah, fb[nt]);
#pragma unroll
                    for (int nt = 0; nt < 4; nt++) MMAH(acc[mt][nt], fal, fb[nt]);
                } else {
#pragma unroll
                    for (int nt = 0; nt < 4; nt++) MMAH(acc[mt][nt], fah, fb[nt]);
                }
            }
        }

        if (kt < K) {
            CP_WAIT0();
            if (MODE == 1) CVT_STS_B(buf ^ 1);
            __syncthreads();
            buf ^= 1;
        }
    }
#undef LOAD_A
#undef LOAD_B0
#undef LDG_B
#undef CVT_STS_B

    const int r0 = warp_m * 64 + (lane >> 2);
    const int c0 = warp_n * 32 + (lane & 3) * 2;

    if (MODE == 1 && blockIdx.y < 2) {
        // ---- q path: softmax over d, write fp16 ----
        __syncthreads();
        float* sf = (float*)smbuf;
#pragma unroll
        for (int mt = 0; mt < 4; mt++)
#pragma unroll
            for (int nt = 0; nt < 4; nt++) {
                int r = r0 + mt * 16, c = c0 + nt * 8;
                sf[r * EPI_PITCH + c]           = acc[mt][nt][0];
                sf[r * EPI_PITCH + c + 1]       = acc[mt][nt][1];
                sf[(r + 8) * EPI_PITCH + c]     = acc[mt][nt][2];
                sf[(r + 8) * EPI_PITCH + c + 1] = acc[mt][nt][3];
            }
        __syncthreads();

        const int col = tid & 127;
        const int h0  = tid >> 7;
        const long n  = bn + col;
#pragma unroll
        for (int hh = h0; hh < 4; hh += 2) {
            float v[DH];
            float mx = -1e30f;
#pragma unroll
            for (int d = 0; d < DH; d++) {
                v[d] = sf[(hh * DH + d) * EPI_PITCH + col];
                mx = fmaxf(mx, v[d]);
            }
            float s = 0.f;
#pragma unroll
            for (int d = 0; d < DH; d++) { v[d] = expf(v[d] - mx); s += v[d]; }
            float inv = 1.f / s;
            const int hglob = blockIdx.y * 4 + hh;
            __half* qp = g_qf + ((long)bz * CDIM + hglob * DH) * NTOK + n;
#pragma unroll
            for (int d = 0; d < DH; d++)
                qp[(long)d * NTOK] = __float2half(v[d] * inv);
        }
    } else if (MODE == 1 && blockIdx.y < 4) {
        // ---- k path: exp -> fp16 store + fp32 partial row sums via smem ----
        __syncthreads();
        float* sf = (float*)smbuf;
#pragma unroll
        for (int mt = 0; mt < 4; mt++)
#pragma unroll
            for (int nt = 0; nt < 4; nt++) {
                int r = r0 + mt * 16, c = c0 + nt * 8;
                float e0 = expf(acc[mt][nt][0]);
                float e1 = expf(acc[mt][nt][1]);
                float e2 = expf(acc[mt][nt][2]);
                float e3 = expf(acc[mt][nt][3]);
                long kr = (blockIdx.y - 2) * 128;
                long i01 = ((long)bz * CDIM + kr + r) * NTOK + bn + c;
                *(uint32_t*)(g_ekf + i01)             = pack_half2(e0, e1);
                *(uint32_t*)(g_ekf + i01 + 8L * NTOK) = pack_half2(e2, e3);
                sf[r * EPI_PITCH + c]           = e0;
                sf[r * EPI_PITCH + c + 1]       = e1;
                sf[(r + 8) * EPI_PITCH + c]     = e2;
                sf[(r + 8) * EPI_PITCH + c + 1] = e3;
            }
        __syncthreads();
        if (tid < 128) {
            float s = 0.f;
#pragma unroll 8
            for (int c = 0; c < 128; c++) s += sf[tid * EPI_PITCH + c];
            int kr = (blockIdx.y - 2) * 128 + tid;
            g_ksum_part[((long)bz * 256 + kr) * 256 + blockIdx.x] = s;
        }
    } else if (MODE == 1) {
        // ---- v path: fp16 store ----
#pragma unroll
        for (int mt = 0; mt < 4; mt++)
#pragma unroll
            for (int nt = 0; nt < 4; nt++) {
                int r = r0 + mt * 16, c = c0 + nt * 8;
                long vr = (blockIdx.y - 4) * 128;
                long i01 = ((long)bz * CDIM + vr + r) * NTOK + bn + c;
                *(uint32_t*)(g_vf + i01)             = pack_half2(acc[mt][nt][0], acc[mt][nt][1]);
                *(uint32_t*)(g_vf + i01 + 8L * NTOK) = pack_half2(acc[mt][nt][2], acc[mt][nt][3]);
            }
    } else {
        // ---- plain fp32 store (GEMM3 output) ----
#pragma unroll
        for (int mt = 0; mt < 4; mt++)
#pragma unroll
            for (int nt = 0; nt < 4; nt++) {
                long row = bm + r0 + mt * 16;
                float* cp = C + row * (long)N + bn + c0 + nt * 8;
                *(float2*)cp               = make_float2(acc[mt][nt][0], acc[mt][nt][1]);
                *(float2*)(cp + 8*(long)N) = make_float2(acc[mt][nt][2], acc[mt][nt][3]);
            }
    }
}

// ---------------------------------------------------------------------------
// fp32 -> (fp16 hi, fp16 lo) split conversion (w_qkv only).
// ---------------------------------------------------------------------------
__global__ void cvt_split(const float* __restrict__ src,
                          __half* __restrict__ h, __half* __restrict__ l,
                          long n)
{
    long i = ((long)blockIdx.x * blockDim.x + threadIdx.x) * 4;
    if (i >= n) return;
    float4 v = *(const float4*)(src + i);
    float a[4] = {v.x, v.y, v.z, v.w};
#pragma unroll
    for (int j = 0; j < 4; j++) {
        __half hh = __float2half(a[j]);
        h[i + j] = hh;
        l[i + j] = __float2half(a[j] - __half2float(hh));
    }
}

// ---------------------------------------------------------------------------
// Reduce per-ntile partial k row sums. Deterministic.
// ---------------------------------------------------------------------------
__global__ void ksum_reduce_kernel()
{
    int b  = blockIdx.x >> 8;
    int kr = blockIdx.x & 255;
    __shared__ float red[256];
    red[threadIdx.x] = g_ksum_part[((long)b * 256 + kr) * 256 + threadIdx.x];
    __syncthreads();
    for (int o = 128; o > 0; o >>= 1) {
        if (threadIdx.x < o) red[threadIdx.x] += red[threadIdx.x + o];
        __syncthreads();
    }
    if (threadIdx.x == 0) g_ksum[b * 256 + kr] = red[0];
}

// ---------------------------------------------------------------------------
// Partial contexts via fp16 mma over 128-token stripes.
// ---------------------------------------------------------------------------
__global__ __launch_bounds__(256)
void ctx_part_kernel()
{
    const int w      = threadIdx.x >> 5;
    const int lane   = threadIdx.x & 31;
    const int stripe = blockIdx.x * 8 + w;     // 0..255
    const int h      = blockIdx.y;
    const int b      = blockIdx.z;
    const int lr = lane >> 2, lc = lane & 3;

    const long chbase = ((long)b * CDIM + h * DH) * NTOK;
    const int  n0 = stripe * 128;

    float acc[2][4][4];
#pragma unroll
    for (int i = 0; i < 2; i++)
#pragma unroll
        for (int j = 0; j < 4; j++)
#pragma unroll
            for (int r = 0; r < 4; r++) acc[i][j][r] = 0.f;

#pragma unroll
    for (int c = 0; c < 4; c++) {
#pragma unroll
        for (int ks = 0; ks < 2; ks++) {
            const long tk = n0 + c * 32 + ks * 16 + lc * 2;
            uint32_t fa[2][4], fb[4][2];
#pragma unroll
            for (int mt = 0; mt < 2; mt++) {
                long r0i = chbase + (long)(mt * 16 + lr) * NTOK + tk;
                long r8i = r0i + 8L * NTOK;
                fa[mt][0] = *(const uint32_t*)(g_ekf + r0i);
                fa[mt][1] = *(const uint32_t*)(g_ekf + r8i);
                fa[mt][2] = *(const uint32_t*)(g_ekf + r0i + 8);
                fa[mt][3] = *(const uint32_t*)(g_ekf + r8i + 8);
            }
#pragma unroll
            for (int nt = 0; nt < 4; nt++) {
                long rbi = chbase + (long)(nt * 8 + lr) * NTOK + tk;
                fb[nt][0] = *(const uint32_t*)(g_vf + rbi);
                fb[nt][1] = *(const uint32_t*)(g_vf + rbi + 8);
            }
#pragma unroll
            for (int mt = 0; mt < 2; mt++)
#pragma unroll
                for (int nt = 0; nt < 4; nt++)
                    MMAH(acc[mt][nt], fa[mt], fb[nt]);
        }
    }

    float* out = g_ctx_part + ((long)((b * HEADS + h) * 256) + stripe) * (DH * DH);
#pragma unroll
    for (int mt = 0; mt < 2; mt++)
#pragma unroll
        for (int nt = 0; nt < 4; nt++) {
            int d0 = mt * 16 + lr, e0 = nt * 8 + lc * 2;
            out[d0 * DH + e0]           = acc[mt][nt][0];
            out[d0 * DH + e0 + 1]       = acc[mt][nt][1];
            out[(d0 + 8) * DH + e0]     = acc[mt][nt][2];
            out[(d0 + 8) * DH + e0 + 1] = acc[mt][nt][3];
        }
}

__global__ void ctx_reduce_kernel()
{
    int idx = blockIdx.x * blockDim.x + threadIdx.x;  // < B_*HEADS*1024
    int de = idx % (DH * DH);
    int bh = idx / (DH * DH);
    int d  = de / DH;
    int b  = bh / HEADS, h = bh % HEADS;
    const float* p = g_ctx_part + (long)bh * 256 * (DH * DH) + de;
    float s = 0.f;
#pragma unroll 8
    for (int st = 0; st < 256; st++) s += p[(long)st * (DH * DH)];
    float inv = 1.f / g_ksum[b * 256 + h * DH + d];
    g_ctx[(long)bh * (DH * DH) + de] = s * inv;
}

// ---------------------------------------------------------------------------
// Fold w_out with context; emit single fp16 W2.
// ---------------------------------------------------------------------------
__global__ void fold_w2_kernel(const float* __restrict__ w_out)
{
    int idx = blockIdx.x * blockDim.x + threadIdx.x;  // < B_*256*256
    int hd = idx % 256;
    int o  = (idx / 256) % 256;
    int b  = idx / 65536;
    int h = hd / DH, d = hd % DH;
    const float* wrow = w_out + o * 256 + h * DH;
    const float* ctx  = g_ctx + ((long)(b * HEADS + h) * DH + d) * DH;
    float s = 0.f;
#pragma unroll
    for (int e = 0; e < DH; e++) s = fmaf(wrow[e], ctx[e], s);
    g_w2[(long)b * 65536 + o * 256 + hd] = __float2half(s);
}

// ---------------------------------------------------------------------------
// Launch
// ---------------------------------------------------------------------------
extern "C" void kernel_launch(void* const* d_in, const int* in_sizes, int n_in,
                              void* d_out, int out_size)
{
    const float* x     = (const float*)d_in[0];  // [2,256,32768]
    const float* w_qkv = (const float*)d_in[1];  // [768,256]
    const float* w_out = (const float*)d_in[2];  // [256,256]
    float* out = (float*)d_out;                  // [2,256,32768]

    __half *wh, *wl, *qf, *w2;
    cudaGetSymbolAddress((void**)&wh, g_wh);
    cudaGetSymbolAddress((void**)&wl, g_wl);
    cudaGetSymbolAddress((void**)&qf, g_qf);
    cudaGetSymbolAddress((void**)&w2, g_w2);

    cudaFuncSetAttribute(gemm_tc<1>, cudaFuncAttributeMaxDynamicSharedMemorySize, GEMM_SMEM);
    cudaFuncSetAttribute(gemm_tc<0>, cudaFuncAttributeMaxDynamicSharedMemorySize, GEMM_SMEM);

    // 0) fp16 hi/lo split of w_qkv
    cvt_split<<<(O1*CDIM/4 + 255)/256, 256>>>(w_qkv, wh, wl, (long)O1*CDIM);

    // 1) qkv = w_qkv @ x; 2-term fp16, fused conversion + q/k/v epilogues
    gemm_tc<1><<<dim3(NTOK/BN, O1/BM, B_), 256, GEMM_SMEM>>>(
        wh, wl, nullptr, x, nullptr, CDIM, NTOK,
        0L, (long)CDIM*NTOK, 0L);

    // 2) finish k row sums
    ksum_reduce_kernel<<<B_ * 256, 256>>>();

    // 3) partial contexts (fp16 tensor-core, fragment-direct loads)
    ctx_part_kernel<<<dim3(32, HEADS, B_), 256>>>();

    // 4) reduce + normalize contexts
    ctx_reduce_kernel<<<(B_ * HEADS * DH * DH) / 256, 256>>>();

    // 5) fold output weight with context -> single fp16 W2
    fold_w2_kernel<<<(B_ * 256 * 256) / 256, 256>>>(w_out);

    // 6) out = W2 @ q  (1-term fp16)
    gemm_tc<0><<<dim3(NTOK/BN, CDIM/BM, B_), 256, GEMM_SMEM>>>(
        w2, nullptr, qf, nullptr, out, CDIM, NTOK,
        (long)CDIM*CDIM, (long)CDIM*NTOK, (long)CDIM*NTOK);
}

// round 16
// speedup vs baseline: 1.6121x; 1.1019x over previous
#include <cuda_runtime.h>
#include <cuda_bf16.h>
#include <cuda_fp16.h>
#include <cstdint>
#include <cstddef>
#include <math.h>

// Problem constants
#define B_    2
#define CDIM  256
#define NTOK  32768          // 32*32*32 tokens
#define HEADS 8
#define DH    32
#define O1    768            // 3 * HEADS * DH

// GEMM tiling
#define BM 128
#define BN 128
#define BK 32
#define APITCH 40            // 32 + 8 fp16 pad  (80B rows -> conflict-free ldmatrix)
#define BPITCH 136           // 128 + 8 fp16 pad (272B rows -> conflict-free ldmatrix.trans)
#define OA 0
#define OB (BM*APITCH)                   // 5120
#define BUFE (BM*APITCH + BK*BPITCH)     // 9472 fp16 elems per stage
#define GEMM_SMEM 66560                  // >= max(2*BUFE*2, 128*129*4 epilogue scratch)
#define EPI_PITCH 129                    // fp32 epilogue scratch pitch

// ctx tiling: 64-token stripes -> 512 stripes (2x parallelism vs R15)
#define NSTRIPE 512
#define STRIPE_TOK 64

// ---------------------------------------------------------------------------
// Scratch (device globals; no cudaMalloc allowed)
// ---------------------------------------------------------------------------
__device__ float g_ksum[B_ * 256];
__device__ float g_ksum_part[B_ * 256 * 256];                    // [b][krow][ntile]
__device__ float g_ctx_part[(size_t)B_ * HEADS * NSTRIPE * DH * DH];
__device__ float g_ctx[B_ * HEADS * DH * DH];
__device__ __align__(16) __half g_ekf[(size_t)B_*CDIM*NTOK];     // exp(k) fp16
__device__ __align__(16) __half g_vf [(size_t)B_*CDIM*NTOK];     // v fp16
__device__ __align__(16) __half g_qf [(size_t)B_*CDIM*NTOK];     // q fp16
__device__ __align__(16) __half g_wf [O1*CDIM];                  // w_qkv fp16 (single)
__device__ __align__(16) __half g_w2[B_*CDIM*CDIM];              // W2 fp16 (single)

// ---------------------------------------------------------------------------
// PTX helpers
// ---------------------------------------------------------------------------
#define CP16(dst, src) \
    asm volatile("cp.async.cg.shared.global [%0], [%1], 16;" :: "r"(dst), "l"(src) : "memory")
#define CP_COMMIT() asm volatile("cp.async.commit_group;" ::: "memory")
#define CP_WAIT0()  asm volatile("cp.async.wait_group 0;"  ::: "memory")

#define LDSM4(r0,r1,r2,r3,a) \
    asm volatile("ldmatrix.sync.aligned.m8n8.x4.shared.b16 {%0,%1,%2,%3}, [%4];" \
                 : "=r"(r0),"=r"(r1),"=r"(r2),"=r"(r3) : "r"(a))
#define LDSM4T(r0,r1,r2,r3,a) \
    asm volatile("ldmatrix.sync.aligned.m8n8.x4.trans.shared.b16 {%0,%1,%2,%3}, [%4];" \
                 : "=r"(r0),"=r"(r1),"=r"(r2),"=r"(r3) : "r"(a))

#define MMAH(d, a, b) \
    asm volatile("mma.sync.aligned.m16n8k16.row.col.f32.f16.f16.f32 " \
                 "{%0,%1,%2,%3},{%4,%5,%6,%7},{%8,%9},{%0,%1,%2,%3};" \
                 : "+f"((d)[0]),"+f"((d)[1]),"+f"((d)[2]),"+f"((d)[3]) \
                 : "r"((a)[0]),"r"((a)[1]),"r"((a)[2]),"r"((a)[3]), \
                   "r"((b)[0]),"r"((b)[1]))

__device__ __forceinline__ uint32_t pack_half2(float a, float b)
{
    __half2 p = __floats2half2_rn(a, b);
    return *(uint32_t*)&p;
}

// ---------------------------------------------------------------------------
// fp16 tensor-core GEMM, single-term (a*b), 128x128x32 tiles, 8 warps.
// MODE 1 (GEMM1): A = w_qkv fp16; B = x fp32 converted to fp16 in-kernel.
//   Fused epilogues: blockIdx.y 0-1 q-softmax -> g_qf; 2-3 exp(k) -> g_ekf +
//   fp32 row sums; 4-5 v -> g_vf.
// MODE 0 (GEMM3): A = W2 fp16; B = q fp16 via cp.async. fp32 epilogue -> C.
// Error model (R13-R15 validated): input quantization at ulp u costs ~0.7u
// relative on the dot product; exp/softmax paths further damp w-quantization.
// ---------------------------------------------------------------------------
template <int MODE>
__global__ __launch_bounds__(256, 2)
void gemm_tc(const __half* __restrict__ Ah,
             const __half* __restrict__ Bh,
             const float* __restrict__ Bf,
             float* __restrict__ C, int K, int N,
             long sA, long sB, long sC)
{
    extern __shared__ __half smbuf[];
    const int bz = blockIdx.z;
    Ah += bz * sA;
    if (MODE == 0) Bh += bz * sB;
    else           Bf += bz * sB;
    C  += bz * sC;

    const int tid   = threadIdx.x;
    const int lane  = tid & 31;
    const int wid   = tid >> 5;
    const int warp_m = wid >> 2;
    const int warp_n = wid & 3;
    const int bn = blockIdx.x * BN;
    const int bm = blockIdx.y * BM;

    const uint32_t su = (uint32_t)__cvta_generic_to_shared(smbuf);

    const int rowA = (lane & 7) + ((lane >> 3) & 1) * 8;
    const int colA = (lane >> 4) * 8;
    const uint32_t aOff = (uint32_t)(((warp_m * 64 + rowA) * APITCH + colA) * 2);
    const int rowB = (lane & 7) + ((lane >> 3) & 1) * 8;
    const int colB = warp_n * 32 + ((lane >> 4) & 1) * 8;
    const uint32_t bOff = (uint32_t)((rowB * BPITCH + colB) * 2);

    float acc[4][4][4];
#pragma unroll
    for (int i = 0; i < 4; i++)
#pragma unroll
        for (int j = 0; j < 4; j++)
#pragma unroll
            for (int r = 0; r < 4; r++) acc[i][j][r] = 0.f;

    float4 breg[4];

    // A: 128x32 fp16 = 512 x 16B -> 2 cp.async per thread
#define LOAD_A(buf, kt) do {                                                         \
    _Pragma("unroll")                                                                \
    for (int p = 0; p < 2; p++) {                                                    \
        int id = tid + p * 256;                                                      \
        int ra = id >> 2, ca = (id & 3) * 8;                                         \
        uint32_t dA = su + (uint32_t)(((buf)*BUFE + OA + ra*APITCH + ca) * 2);       \
        CP16(dA, Ah + (long)(bm + ra) * K + (kt) + ca);                              \
    }                                                                                \
} while (0)

    // MODE 0: fp16 B plane (q) via cp.async (32x128 fp16 = 512 x 16B)
#define LOAD_B0(buf, kt) do {                                                        \
    _Pragma("unroll")                                                                \
    for (int p = 0; p < 2; p++) {                                                    \
        int id = tid + p * 256;                                                      \
        int rb = id >> 4, cb = (id & 15) * 8;                                        \
        uint32_t dB = su + (uint32_t)(((buf)*BUFE + OB + rb*BPITCH + cb) * 2);       \
        CP16(dB, Bh + (long)((kt) + rb) * N + bn + cb);                              \
    }                                                                                \
} while (0)

#define LDG_B(kt) do {                                                               \
    _Pragma("unroll")                                                                \
    for (int p = 0; p < 4; p++) {                                                    \
        int id = tid + p * 256;                                                      \
        int rb = id >> 5, cb = (id & 31) * 4;                                        \
        breg[p] = *(const float4*)(Bf + (long)((kt) + rb) * N + bn + cb);            \
    }                                                                                \
} while (0)

#define CVT_STS_B(buf) do {                                                          \
    _Pragma("unroll")                                                                \
    for (int p = 0; p < 4; p++) {                                                    \
        int id = tid + p * 256;                                                      \
        int rb = id >> 5, cb = (id & 31) * 4;                                        \
        uint32_t lohi[2];                                                            \
        lohi[0] = pack_half2(breg[p].x, breg[p].y);                                  \
        lohi[1] = pack_half2(breg[p].z, breg[p].w);                                  \
        __half* bp = smbuf + (buf)*BUFE + OB + rb*BPITCH + cb;                       \
        *(uint2*)bp = *(uint2*)lohi;                                                 \
    }                                                                                \
} while (0)

    LOAD_A(0, 0);
    if (MODE == 0) LOAD_B0(0, 0);
    CP_COMMIT();
    if (MODE == 1) LDG_B(0);
    CP_WAIT0();
    if (MODE == 1) CVT_STS_B(0);
    __syncthreads();

    int buf = 0;
    for (int kt = BK; kt <= K; kt += BK) {
        if (kt < K) {
            LOAD_A(buf ^ 1, kt);
            if (MODE == 0) LOAD_B0(buf ^ 1, kt);
            CP_COMMIT();
            if (MODE == 1) LDG_B(kt);
        }

        const uint32_t stage = su + (uint32_t)(buf * BUFE * 2);
#pragma unroll
        for (int kk = 0; kk < BK; kk += 16) {
            uint32_t fb[4][2];
#pragma unroll
            for (int pr = 0; pr < 2; pr++) {
                uint32_t ad = stage + (uint32_t)(OB*2) + (uint32_t)(kk*BPITCH*2) + bOff + (uint32_t)(pr*32);
                LDSM4T(fb[2*pr][0], fb[2*pr][1], fb[2*pr+1][0], fb[2*pr+1][1], ad);
            }
#pragma unroll
            for (int mt = 0; mt < 4; mt++) {
                uint32_t fa[4];
                uint32_t aa = stage + (uint32_t)(OA*2) + aOff + (uint32_t)((mt*16*APITCH + kk) * 2);
                LDSM4(fa[0], fa[1], fa[2], fa[3], aa);
#pragma unroll
                for (int nt = 0; nt < 4; nt++) MMAH(acc[mt][nt], fa, fb[nt]);
            }
        }

        if (kt < K) {
            CP_WAIT0();
            if (MODE == 1) CVT_STS_B(buf ^ 1);
            __syncthreads();
            buf ^= 1;
        }
    }
#undef LOAD_A
#undef LOAD_B0
#undef LDG_B
#undef CVT_STS_B

    const int r0 = warp_m * 64 + (lane >> 2);
    const int c0 = warp_n * 32 + (lane & 3) * 2;

    if (MODE == 1 && blockIdx.y < 2) {
        // ---- q path: softmax over d, write fp16 ----
        __syncthreads();
        float* sf = (float*)smbuf;
#pragma unroll
        for (int mt = 0; mt < 4; mt++)
#pragma unroll
            for (int nt = 0; nt < 4; nt++) {
                int r = r0 + mt * 16, c = c0 + nt * 8;
                sf[r * EPI_PITCH + c]           = acc[mt][nt][0];
                sf[r * EPI_PITCH + c + 1]       = acc[mt][nt][1];
                sf[(r + 8) * EPI_PITCH + c]     = acc[mt][nt][2];
                sf[(r + 8) * EPI_PITCH + c + 1] = acc[mt][nt][3];
            }
        __syncthreads();

        const int col = tid & 127;
        const int h0  = tid >> 7;
        const long n  = bn + col;
#pragma unroll
        for (int hh = h0; hh < 4; hh += 2) {
            float v[DH];
            float mx = -1e30f;
#pragma unroll
            for (int d = 0; d < DH; d++) {
                v[d] = sf[(hh * DH + d) * EPI_PITCH + col];
                mx = fmaxf(mx, v[d]);
            }
            float s = 0.f;
#pragma unroll
            for (int d = 0; d < DH; d++) { v[d] = expf(v[d] - mx); s += v[d]; }
            float inv = 1.f / s;
            const int hglob = blockIdx.y * 4 + hh;
            __half* qp = g_qf + ((long)bz * CDIM + hglob * DH) * NTOK + n;
#pragma unroll
            for (int d = 0; d < DH; d++)
                qp[(long)d * NTOK] = __float2half(v[d] * inv);
        }
    } else if (MODE == 1 && blockIdx.y < 4) {
        // ---- k path: exp -> fp16 store + fp32 partial row sums via smem ----
        __syncthreads();
        float* sf = (float*)smbuf;
#pragma unroll
        for (int mt = 0; mt < 4; mt++)
#pragma unroll
            for (int nt = 0; nt < 4; nt++) {
                int r = r0 + mt * 16, c = c0 + nt * 8;
                float e0 = expf(acc[mt][nt][0]);
                float e1 = expf(acc[mt][nt][1]);
                float e2 = expf(acc[mt][nt][2]);
                float e3 = expf(acc[mt][nt][3]);
                long kr = (blockIdx.y - 2) * 128;
                long i01 = ((long)bz * CDIM + kr + r) * NTOK + bn + c;
                *(uint32_t*)(g_ekf + i01)             = pack_half2(e0, e1);
                *(uint32_t*)(g_ekf + i01 + 8L * NTOK) = pack_half2(e2, e3);
                sf[r * EPI_PITCH + c]           = e0;
                sf[r * EPI_PITCH + c + 1]       = e1;
                sf[(r + 8) * EPI_PITCH + c]     = e2;
                sf[(r + 8) * EPI_PITCH + c + 1] = e3;
            }
        __syncthreads();
        if (tid < 128) {
            float s = 0.f;
#pragma unroll 8
            for (int c = 0; c < 128; c++) s += sf[tid * EPI_PITCH + c];
            int kr = (blockIdx.y - 2) * 128 + tid;
            g_ksum_part[((long)bz * 256 + kr) * 256 + blockIdx.x] = s;
        }
    } else if (MODE == 1) {
        // ---- v path: fp16 store ----
#pragma unroll
        for (int mt = 0; mt < 4; mt++)
#pragma unroll
            for (int nt = 0; nt < 4; nt++) {
                int r = r0 + mt * 16, c = c0 + nt * 8;
                long vr = (blockIdx.y - 4) * 128;
                long i01 = ((long)bz * CDIM + vr + r) * NTOK + bn + c;
                *(uint32_t*)(g_vf + i01)             = pack_half2(acc[mt][nt][0], acc[mt][nt][1]);
                *(uint32_t*)(g_vf + i01 + 8L * NTOK) = pack_half2(acc[mt][nt][2], acc[mt][nt][3]);
            }
    } else {
        // ---- plain fp32 store (GEMM3 output) ----
#pragma unroll
        for (int mt = 0; mt < 4; mt++)
#pragma unroll
            for (int nt = 0; nt < 4; nt++) {
                long row = bm + r0 + mt * 16;
                float* cp = C + row * (long)N + bn + c0 + nt * 8;
                *(float2*)cp               = make_float2(acc[mt][nt][0], acc[mt][nt][1]);
                *(float2*)(cp + 8*(long)N) = make_float2(acc[mt][nt][2], acc[mt][nt][3]);
            }
    }
}

// ---------------------------------------------------------------------------
// fp32 -> fp16 conversion (w_qkv only).
// ---------------------------------------------------------------------------
__global__ void cvt_half(const float* __restrict__ src,
                         __half* __restrict__ h, long n)
{
    long i = ((long)blockIdx.x * blockDim.x + threadIdx.x) * 4;
    if (i >= n) return;
    float4 v = *(const float4*)(src + i);
    uint32_t lohi[2];
    lohi[0] = pack_half2(v.x, v.y);
    lohi[1] = pack_half2(v.z, v.w);
    *(uint2*)(h + i) = *(uint2*)lohi;
}

// ---------------------------------------------------------------------------
// Reduce per-ntile partial k row sums. Deterministic.
// ---------------------------------------------------------------------------
__global__ void ksum_reduce_kernel()
{
    int b  = blockIdx.x >> 8;
    int kr = blockIdx.x & 255;
    __shared__ float red[256];
    red[threadIdx.x] = g_ksum_part[((long)b * 256 + kr) * 256 + threadIdx.x];
    __syncthreads();
    for (int o = 128; o > 0; o >>= 1) {
        if (threadIdx.x < o) red[threadIdx.x] += red[threadIdx.x + o];
        __syncthreads();
    }
    if (threadIdx.x == 0) g_ksum[b * 256 + kr] = red[0];
}

// ---------------------------------------------------------------------------
// Partial contexts via fp16 mma over 64-token stripes (512 stripes -> 2x
// warp parallelism vs 128-token version; ctx_part was latency-bound at
// issue=4.3%, occ=39%).
// ---------------------------------------------------------------------------
__global__ __launch_bounds__(256)
void ctx_part_kernel()
{
    const int w      = threadIdx.x >> 5;
    const int lane   = threadIdx.x & 31;
    const int stripe = blockIdx.x * 8 + w;     // 0..511
    const int h      = blockIdx.y;
    const int b      = blockIdx.z;
    const int lr = lane >> 2, lc = lane & 3;

    const long chbase = ((long)b * CDIM + h * DH) * NTOK;
    const int  n0 = stripe * STRIPE_TOK;

    float acc[2][4][4];
#pragma unroll
    for (int i = 0; i < 2; i++)
#pragma unroll
        for (int j = 0; j < 4; j++)
#pragma unroll
            for (int r = 0; r < 4; r++) acc[i][j][r] = 0.f;

#pragma unroll
    for (int c = 0; c < 2; c++) {
#pragma unroll
        for (int ks = 0; ks < 2; ks++) {
            const long tk = n0 + c * 32 + ks * 16 + lc * 2;
            uint32_t fa[2][4], fb[4][2];
#pragma unroll
            for (int mt = 0; mt < 2; mt++) {
                long r0i = chbase + (long)(mt * 16 + lr) * NTOK + tk;
                long r8i = r0i + 8L * NTOK;
                fa[mt][0] = *(const uint32_t*)(g_ekf + r0i);
                fa[mt][1] = *(const uint32_t*)(g_ekf + r8i);
                fa[mt][2] = *(const uint32_t*)(g_ekf + r0i + 8);
                fa[mt][3] = *(const uint32_t*)(g_ekf + r8i + 8);
            }
#pragma unroll
            for (int nt = 0; nt < 4; nt++) {
                long rbi = chbase + (long)(nt * 8 + lr) * NTOK + tk;
                fb[nt][0] = *(const uint32_t*)(g_vf + rbi);
                fb[nt][1] = *(const uint32_t*)(g_vf + rbi + 8);
            }
#pragma unroll
            for (int mt = 0; mt < 2; mt++)
#pragma unroll
                for (int nt = 0; nt < 4; nt++)
                    MMAH(acc[mt][nt], fa[mt], fb[nt]);
        }
    }

    float* out = g_ctx_part + ((long)((b * HEADS + h) * NSTRIPE) + stripe) * (DH * DH);
#pragma unroll
    for (int mt = 0; mt < 2; mt++)
#pragma unroll
        for (int nt = 0; nt < 4; nt++) {
            int d0 = mt * 16 + lr, e0 = nt * 8 + lc * 2;
            out[d0 * DH + e0]           = acc[mt][nt][0];
            out[d0 * DH + e0 + 1]       = acc[mt][nt][1];
            out[(d0 + 8) * DH + e0]     = acc[mt][nt][2];
            out[(d0 + 8) * DH + e0 + 1] = acc[mt][nt][3];
        }
}

__global__ void ctx_reduce_kernel()
{
    int idx = blockIdx.x * blockDim.x + threadIdx.x;  // < B_*HEADS*1024
    int de = idx % (DH * DH);
    int bh = idx / (DH * DH);
    int d  = de / DH;
    int b  = bh / HEADS, h = bh % HEADS;
    const float* p = g_ctx_part + (long)bh * NSTRIPE * (DH * DH) + de;
    float s = 0.f;
#pragma unroll 8
    for (int st = 0; st < NSTRIPE; st++) s += p[(long)st * (DH * DH)];
    float inv = 1.f / g_ksum[b * 256 + h * DH + d];
    g_ctx[(long)bh * (DH * DH) + de] = s * inv;
}

// ---------------------------------------------------------------------------
// Fold w_out with context; emit single fp16 W2.
// ---------------------------------------------------------------------------
__global__ void fold_w2_kernel(const float* __restrict__ w_out)
{
    int idx = blockIdx.x * blockDim.x + threadIdx.x;  // < B_*256*256
    int hd = idx % 256;
    int o  = (idx / 256) % 256;
    int b  = idx / 65536;
    int h = hd / DH, d = hd % DH;
    const float* wrow = w_out + o * 256 + h * DH;
    const float* ctx  = g_ctx + ((long)(b * HEADS + h) * DH + d) * DH;
    float s = 0.f;
#pragma unroll
    for (int e = 0; e < DH; e++) s = fmaf(wrow[e], ctx[e], s);
    g_w2[(long)b * 65536 + o * 256 + hd] = __float2half(s);
}

// ---------------------------------------------------------------------------
// Launch
// ---------------------------------------------------------------------------
extern "C" void kernel_launch(void* const* d_in, const int* in_sizes, int n_in,
                              void* d_out, int out_size)
{
    const float* x     = (const float*)d_in[0];  // [2,256,32768]
    const float* w_qkv = (const float*)d_in[1];  // [768,256]
    const float* w_out = (const float*)d_in[2];  // [256,256]
    float* out = (float*)d_out;                  // [2,256,32768]

    __half *wf, *qf, *w2;
    cudaGetSymbolAddress((void**)&wf, g_wf);
    cudaGetSymbolAddress((void**)&qf, g_qf);
    cudaGetSymbolAddress((void**)&w2, g_w2);

    cudaFuncSetAttribute(gemm_tc<1>, cudaFuncAttributeMaxDynamicSharedMemorySize, GEMM_SMEM);
    cudaFuncSetAttribute(gemm_tc<0>, cudaFuncAttributeMaxDynamicSharedMemorySize, GEMM_SMEM);

    // 0) fp16 conversion of w_qkv
    cvt_half<<<(O1*CDIM/4 + 255)/256, 256>>>(w_qkv, wf, (long)O1*CDIM);

    // 1) qkv = w_qkv @ x; 1-term fp16, fused conversion + q/k/v epilogues
    gemm_tc<1><<<dim3(NTOK/BN, O1/BM, B_), 256, GEMM_SMEM>>>(
        wf, nullptr, x, nullptr, CDIM, NTOK,
        0L, (long)CDIM*NTOK, 0L);

    // 2) finish k row sums
    ksum_reduce_kernel<<<B_ * 256, 256>>>();

    // 3) partial contexts (fp16 tensor-core, 64-token stripes)
    ctx_part_kernel<<<dim3(NSTRIPE/8, HEADS, B_), 256>>>();

    // 4) reduce + normalize contexts
    ctx_reduce_kernel<<<(B_ * HEADS * DH * DH) / 256, 256>>>();

    // 5) fold output weight with context -> single fp16 W2
    fold_w2_kernel<<<(B_ * 256 * 256) / 256, 256>>>(w_out);

    // 6) out = W2 @ q  (1-term fp16)
    gemm_tc<0><<<dim3(NTOK/BN, CDIM/BM, B_), 256, GEMM_SMEM>>>(
        w2, qf, nullptr, out, CDIM, NTOK,
        (long)CDIM*CDIM, (long)CDIM*NTOK, (long)CDIM*NTOK);
}

// round 17
// speedup vs baseline: 1.8236x; 1.1312x over previous
#include <cuda_runtime.h>
#include <cuda_bf16.h>
#include <cuda_fp16.h>
#include <cstdint>
#include <cstddef>
#include <math.h>

// Problem constants
#define B_    2
#define CDIM  256
#define NTOK  32768          // 32*32*32 tokens
#define HEADS 8
#define DH    32
#define O1    768            // 3 * HEADS * DH

// GEMM tiling
#define BM 128
#define BN 128
#define BK 32
#define APITCH 40            // 32 + 8 fp16 pad  (80B rows -> conflict-free ldmatrix)
#define BPITCH 136           // 128 + 8 fp16 pad (272B rows -> conflict-free ldmatrix.trans)
#define OA 0
#define OB (BM*APITCH)                   // 5120
#define BUFE (BM*APITCH + BK*BPITCH)     // 9472 fp16 elems per stage
#define GEMM_SMEM 66560                  // >= max(2*BUFE*2, 128*129*4 epilogue scratch)
#define EPI_PITCH 129                    // fp32 epilogue scratch pitch

// ctx tiling: 128-token stripes, cp.async-staged (MLP fix for latency binding)
#define NSTRIPE 256
#define STRIPE_TOK 128
#define CTX_PITCH 136                    // 128 + 8 fp16 pad (272B rows)
#define CTX_TILE (32*CTX_PITCH)          // halves per 32x128 tile
#define CTX_SMEM (4*2*CTX_TILE*2)        // 4 warps x (ek+v) tiles = 69632 B

// ---------------------------------------------------------------------------
// Scratch (device globals; no cudaMalloc allowed)
// ---------------------------------------------------------------------------
__device__ float g_ksum[B_ * 256];
__device__ float g_ksum_part[B_ * 256 * 256];                    // [b][krow][ntile]
__device__ float g_ctx_part[(size_t)B_ * HEADS * NSTRIPE * DH * DH];
__device__ float g_ctx[B_ * HEADS * DH * DH];
__device__ __align__(16) __half g_ekf[(size_t)B_*CDIM*NTOK];     // exp(k) fp16
__device__ __align__(16) __half g_vf [(size_t)B_*CDIM*NTOK];     // v fp16
__device__ __align__(16) __half g_qf [(size_t)B_*CDIM*NTOK];     // q fp16
__device__ __align__(16) __half g_wf [O1*CDIM];                  // w_qkv fp16
__device__ __align__(16) __half g_w2[B_*CDIM*CDIM];              // W2 fp16

// ---------------------------------------------------------------------------
// PTX helpers
// ---------------------------------------------------------------------------
#define CP16(dst, src) \
    asm volatile("cp.async.cg.shared.global [%0], [%1], 16;" :: "r"(dst), "l"(src) : "memory")
#define CP_COMMIT() asm volatile("cp.async.commit_group;" ::: "memory")
#define CP_WAIT0()  asm volatile("cp.async.wait_group 0;"  ::: "memory")

#define LDSM4(r0,r1,r2,r3,a) \
    asm volatile("ldmatrix.sync.aligned.m8n8.x4.shared.b16 {%0,%1,%2,%3}, [%4];" \
                 : "=r"(r0),"=r"(r1),"=r"(r2),"=r"(r3) : "r"(a))
#define LDSM4T(r0,r1,r2,r3,a) \
    asm volatile("ldmatrix.sync.aligned.m8n8.x4.trans.shared.b16 {%0,%1,%2,%3}, [%4];" \
                 : "=r"(r0),"=r"(r1),"=r"(r2),"=r"(r3) : "r"(a))

#define MMAH(d, a, b) \
    asm volatile("mma.sync.aligned.m16n8k16.row.col.f32.f16.f16.f32 " \
                 "{%0,%1,%2,%3},{%4,%5,%6,%7},{%8,%9},{%0,%1,%2,%3};" \
                 : "+f"((d)[0]),"+f"((d)[1]),"+f"((d)[2]),"+f"((d)[3]) \
                 : "r"((a)[0]),"r"((a)[1]),"r"((a)[2]),"r"((a)[3]), \
                   "r"((b)[0]),"r"((b)[1]))

__device__ __forceinline__ uint32_t pack_half2(float a, float b)
{
    __half2 p = __floats2half2_rn(a, b);
    return *(uint32_t*)&p;
}

// ---------------------------------------------------------------------------
// fp16 tensor-core GEMM, single-term (a*b), 128x128x32 tiles, 8 warps.
// MODE 1 (GEMM1): A = w_qkv fp16; B = x fp32 converted to fp16 in-kernel.
//   Fused epilogues: blockIdx.y 0-1 q-softmax -> g_qf; 2-3 exp(k) -> g_ekf +
//   fp32 row sums; 4-5 v -> g_vf.
// MODE 0 (GEMM3): A = W2 fp16; B = q fp16 via cp.async. fp32 epilogue -> C.
// ---------------------------------------------------------------------------
template <int MODE>
__global__ __launch_bounds__(256, 2)
void gemm_tc(const __half* __restrict__ Ah,
             const __half* __restrict__ Bh,
             const float* __restrict__ Bf,
             float* __restrict__ C, int K, int N,
             long sA, long sB, long sC)
{
    extern __shared__ __half smbuf[];
    const int bz = blockIdx.z;
    Ah += bz * sA;
    if (MODE == 0) Bh += bz * sB;
    else           Bf += bz * sB;
    C  += bz * sC;

    const int tid   = threadIdx.x;
    const int lane  = tid & 31;
    const int wid   = tid >> 5;
    const int warp_m = wid >> 2;
    const int warp_n = wid & 3;
    const int bn = blockIdx.x * BN;
    const int bm = blockIdx.y * BM;

    const uint32_t su = (uint32_t)__cvta_generic_to_shared(smbuf);

    const int rowA = (lane & 7) + ((lane >> 3) & 1) * 8;
    const int colA = (lane >> 4) * 8;
    const uint32_t aOff = (uint32_t)(((warp_m * 64 + rowA) * APITCH + colA) * 2);
    const int rowB = (lane & 7) + ((lane >> 3) & 1) * 8;
    const int colB = warp_n * 32 + ((lane >> 4) & 1) * 8;
    const uint32_t bOff = (uint32_t)((rowB * BPITCH + colB) * 2);

    float acc[4][4][4];
#pragma unroll
    for (int i = 0; i < 4; i++)
#pragma unroll
        for (int j = 0; j < 4; j++)
#pragma unroll
            for (int r = 0; r < 4; r++) acc[i][j][r] = 0.f;

    float4 breg[4];

#define LOAD_A(buf, kt) do {                                                         \
    _Pragma("unroll")                                                                \
    for (int p = 0; p < 2; p++) {                                                    \
        int id = tid + p * 256;                                                      \
        int ra = id >> 2, ca = (id & 3) * 8;                                         \
        uint32_t dA = su + (uint32_t)(((buf)*BUFE + OA + ra*APITCH + ca) * 2);       \
        CP16(dA, Ah + (long)(bm + ra) * K + (kt) + ca);                              \
    }                                                                                \
} while (0)

#define LOAD_B0(buf, kt) do {                                                        \
    _Pragma("unroll")                                                                \
    for (int p = 0; p < 2; p++) {                                                    \
        int id = tid + p * 256;                                                      \
        int rb = id >> 4, cb = (id & 15) * 8;                                        \
        uint32_t dB = su + (uint32_t)(((buf)*BUFE + OB + rb*BPITCH + cb) * 2);       \
        CP16(dB, Bh + (long)((kt) + rb) * N + bn + cb);                              \
    }                                                                                \
} while (0)

#define LDG_B(kt) do {                                                               \
    _Pragma("unroll")                                                                \
    for (int p = 0; p < 4; p++) {                                                    \
        int id = tid + p * 256;                                                      \
        int rb = id >> 5, cb = (id & 31) * 4;                                        \
        breg[p] = *(const float4*)(Bf + (long)((kt) + rb) * N + bn + cb);            \
    }                                                                                \
} while (0)

#define CVT_STS_B(buf) do {                                                          \
    _Pragma("unroll")                                                                \
    for (int p = 0; p < 4; p++) {                                                    \
        int id = tid + p * 256;                                                      \
        int rb = id >> 5, cb = (id & 31) * 4;                                        \
        uint32_t lohi[2];                                                            \
        lohi[0] = pack_half2(breg[p].x, breg[p].y);                                  \
        lohi[1] = pack_half2(breg[p].z, breg[p].w);                                  \
        __half* bp = smbuf + (buf)*BUFE + OB + rb*BPITCH + cb;                       \
        *(uint2*)bp = *(uint2*)lohi;                                                 \
    }                                                                                \
} while (0)

    LOAD_A(0, 0);
    if (MODE == 0) LOAD_B0(0, 0);
    CP_COMMIT();
    if (MODE == 1) LDG_B(0);
    CP_WAIT0();
    if (MODE == 1) CVT_STS_B(0);
    __syncthreads();

    int buf = 0;
    for (int kt = BK; kt <= K; kt += BK) {
        if (kt < K) {
            LOAD_A(buf ^ 1, kt);
            if (MODE == 0) LOAD_B0(buf ^ 1, kt);
            CP_COMMIT();
            if (MODE == 1) LDG_B(kt);
        }

        const uint32_t stage = su + (uint32_t)(buf * BUFE * 2);
#pragma unroll
        for (int kk = 0; kk < BK; kk += 16) {
            uint32_t fb[4][2];
#pragma unroll
            for (int pr = 0; pr < 2; pr++) {
                uint32_t ad = stage + (uint32_t)(OB*2) + (uint32_t)(kk*BPITCH*2) + bOff + (uint32_t)(pr*32);
                LDSM4T(fb[2*pr][0], fb[2*pr][1], fb[2*pr+1][0], fb[2*pr+1][1], ad);
            }
#pragma unroll
            for (int mt = 0; mt < 4; mt++) {
                uint32_t fa[4];
                uint32_t aa = stage + (uint32_t)(OA*2) + aOff + (uint32_t)((mt*16*APITCH + kk) * 2);
                LDSM4(fa[0], fa[1], fa[2], fa[3], aa);
#pragma unroll
                for (int nt = 0; nt < 4; nt++) MMAH(acc[mt][nt], fa, fb[nt]);
            }
        }

        if (kt < K) {
            CP_WAIT0();
            if (MODE == 1) CVT_STS_B(buf ^ 1);
            __syncthreads();
            buf ^= 1;
        }
    }
#undef LOAD_A
#undef LOAD_B0
#undef LDG_B
#undef CVT_STS_B

    const int r0 = warp_m * 64 + (lane >> 2);
    const int c0 = warp_n * 32 + (lane & 3) * 2;

    if (MODE == 1 && blockIdx.y < 2) {
        // ---- q path: softmax over d, write fp16 ----
        __syncthreads();
        float* sf = (float*)smbuf;
#pragma unroll
        for (int mt = 0; mt < 4; mt++)
#pragma unroll
            for (int nt = 0; nt < 4; nt++) {
                int r = r0 + mt * 16, c = c0 + nt * 8;
                sf[r * EPI_PITCH + c]           = acc[mt][nt][0];
                sf[r * EPI_PITCH + c + 1]       = acc[mt][nt][1];
                sf[(r + 8) * EPI_PITCH + c]     = acc[mt][nt][2];
                sf[(r + 8) * EPI_PITCH + c + 1] = acc[mt][nt][3];
            }
        __syncthreads();

        const int col = tid & 127;
        const int h0  = tid >> 7;
        const long n  = bn + col;
#pragma unroll
        for (int hh = h0; hh < 4; hh += 2) {
            float v[DH];
            float mx = -1e30f;
#pragma unroll
            for (int d = 0; d < DH; d++) {
                v[d] = sf[(hh * DH + d) * EPI_PITCH + col];
                mx = fmaxf(mx, v[d]);
            }
            float s = 0.f;
#pragma unroll
            for (int d = 0; d < DH; d++) { v[d] = expf(v[d] - mx); s += v[d]; }
            float inv = 1.f / s;
            const int hglob = blockIdx.y * 4 + hh;
            __half* qp = g_qf + ((long)bz * CDIM + hglob * DH) * NTOK + n;
#pragma unroll
            for (int d = 0; d < DH; d++)
                qp[(long)d * NTOK] = __float2half(v[d] * inv);
        }
    } else if (MODE == 1 && blockIdx.y < 4) {
        // ---- k path: exp -> fp16 store + fp32 partial row sums via smem ----
        __syncthreads();
        float* sf = (float*)smbuf;
#pragma unroll
        for (int mt = 0; mt < 4; mt++)
#pragma unroll
            for (int nt = 0; nt < 4; nt++) {
                int r = r0 + mt * 16, c = c0 + nt * 8;
                float e0 = expf(acc[mt][nt][0]);
                float e1 = expf(acc[mt][nt][1]);
                float e2 = expf(acc[mt][nt][2]);
                float e3 = expf(acc[mt][nt][3]);
                long kr = (blockIdx.y - 2) * 128;
                long i01 = ((long)bz * CDIM + kr + r) * NTOK + bn + c;
                *(uint32_t*)(g_ekf + i01)             = pack_half2(e0, e1);
                *(uint32_t*)(g_ekf + i01 + 8L * NTOK) = pack_half2(e2, e3);
                sf[r * EPI_PITCH + c]           = e0;
                sf[r * EPI_PITCH + c + 1]       = e1;
                sf[(r + 8) * EPI_PITCH + c]     = e2;
                sf[(r + 8) * EPI_PITCH + c + 1] = e3;
            }
        __syncthreads();
        if (tid < 128) {
            float s = 0.f;
#pragma unroll 8
            for (int c = 0; c < 128; c++) s += sf[tid * EPI_PITCH + c];
            int kr = (blockIdx.y - 2) * 128 + tid;
            g_ksum_part[((long)bz * 256 + kr) * 256 + blockIdx.x] = s;
        }
    } else if (MODE == 1) {
        // ---- v path: fp16 store ----
#pragma unroll
        for (int mt = 0; mt < 4; mt++)
#pragma unroll
            for (int nt = 0; nt < 4; nt++) {
                int r = r0 + mt * 16, c = c0 + nt * 8;
                long vr = (blockIdx.y - 4) * 128;
                long i01 = ((long)bz * CDIM + vr + r) * NTOK + bn + c;
                *(uint32_t*)(g_vf + i01)             = pack_half2(acc[mt][nt][0], acc[mt][nt][1]);
                *(uint32_t*)(g_vf + i01 + 8L * NTOK) = pack_half2(acc[mt][nt][2], acc[mt][nt][3]);
            }
    } else {
        // ---- plain fp32 store (GEMM3 output) ----
#pragma unroll
        for (int mt = 0; mt < 4; mt++)
#pragma unroll
            for (int nt = 0; nt < 4; nt++) {
                long row = bm + r0 + mt * 16;
                float* cp = C + row * (long)N + bn + c0 + nt * 8;
                *(float2*)cp               = make_float2(acc[mt][nt][0], acc[mt][nt][1]);
                *(float2*)(cp + 8*(long)N) = make_float2(acc[mt][nt][2], acc[mt][nt][3]);
            }
    }
}

// ---------------------------------------------------------------------------
// fp32 -> fp16 conversion (w_qkv only).
// ---------------------------------------------------------------------------
__global__ void cvt_half(const float* __restrict__ src,
                         __half* __restrict__ h, long n)
{
    long i = ((long)blockIdx.x * blockDim.x + threadIdx.x) * 4;
    if (i >= n) return;
    float4 v = *(const float4*)(src + i);
    uint32_t lohi[2];
    lohi[0] = pack_half2(v.x, v.y);
    lohi[1] = pack_half2(v.z, v.w);
    *(uint2*)(h + i) = *(uint2*)lohi;
}

// ---------------------------------------------------------------------------
// Reduce per-ntile partial k row sums. Deterministic.
// ---------------------------------------------------------------------------
__global__ void ksum_reduce_kernel()
{
    int b  = blockIdx.x >> 8;
    int kr = blockIdx.x & 255;
    __shared__ float red[256];
    red[threadIdx.x] = g_ksum_part[((long)b * 256 + kr) * 256 + threadIdx.x];
    __syncthreads();
    for (int o = 128; o > 0; o >>= 1) {
        if (threadIdx.x < o) red[threadIdx.x] += red[threadIdx.x + o];
        __syncthreads();
    }
    if (threadIdx.x == 0) g_ksum[b * 256 + kr] = red[0];
}

// ---------------------------------------------------------------------------
// Partial contexts over 128-token stripes, cp.async-staged.
// One warp per stripe (4 warps/block, per-warp async groups, no block sync).
// Stage ek/v 32x128 fp16 tiles (pitch 136 -> conflict-free ldmatrix), then
// 8 k-steps of ldmatrix + m16n8k16 MMAs. MLP: 32x 16B cp.async per lane vs
// the 24 dependent LDG.32s that left R16's version latency-bound (issue 4.5%).
// ---------------------------------------------------------------------------
__global__ __launch_bounds__(128)
void ctx_part_kernel()
{
    extern __shared__ __half cs[];
    const int w      = threadIdx.x >> 5;
    const int lane   = threadIdx.x & 31;
    const int stripe = blockIdx.x * 4 + w;     // 0..255
    const int h      = blockIdx.y;
    const int b      = blockIdx.z;
    const int lr = lane >> 2, lc = lane & 3;

    __half* ek_s = cs + (size_t)w * 2 * CTX_TILE;
    __half* v_s  = ek_s + CTX_TILE;
    const uint32_t ek_su = (uint32_t)__cvta_generic_to_shared(ek_s);
    const uint32_t v_su  = (uint32_t)__cvta_generic_to_shared(v_s);

    const long chbase = ((long)b * CDIM + h * DH) * NTOK + (long)stripe * STRIPE_TOK;

    // Stage both tiles: 32 rows x 16 chunks(16B) per tile, 16 chunks/lane/tile.
#pragma unroll
    for (int i = 0; i < 16; i++) {
        int id = lane + i * 32;
        int row = id >> 4, c16 = id & 15;
        uint32_t off = (uint32_t)((row * CTX_PITCH + c16 * 8) * 2);
        const long gsrc = chbase + (long)row * NTOK + c16 * 8;
        CP16(ek_su + off, g_ekf + gsrc);
        CP16(v_su  + off, g_vf  + gsrc);
    }
    CP_COMMIT();
    CP_WAIT0();
    __syncwarp();

    float acc[2][4][4];
#pragma unroll
    for (int i = 0; i < 2; i++)
#pragma unroll
        for (int j = 0; j < 4; j++)
#pragma unroll
            for (int r = 0; r < 4; r++) acc[i][j][r] = 0.f;

    const int mat = lane >> 3;                 // 0..3

#pragma unroll
    for (int kk = 0; kk < STRIPE_TOK; kk += 16) {
        uint32_t fa[2][4], fb[4][2];
        // A frags: mats = (rows mt*16+{0,8}, k halves {0,8})
#pragma unroll
        for (int mt = 0; mt < 2; mt++) {
            int row = mt * 16 + (mat & 1) * 8 + (lane & 7);
            int col = kk + (mat >> 1) * 8;
            LDSM4(fa[mt][0], fa[mt][1], fa[mt][2], fa[mt][3],
                  ek_su + (uint32_t)((row * CTX_PITCH + col) * 2));
        }
        // B frags: mats = (n rows p*16+{0,8}, k halves {0,8}); non-trans on [n][k]
#pragma unroll
        for (int p = 0; p < 2; p++) {
            int row = p * 16 + (mat >> 1) * 8 + (lane & 7);
            int col = kk + (mat & 1) * 8;
            LDSM4(fb[p*2][0], fb[p*2][1], fb[p*2+1][0], fb[p*2+1][1],
                  v_su + (uint32_t)((row * CTX_PITCH + col) * 2));
        }
#pragma unroll
        for (int mt = 0; mt < 2; mt++)
#pragma unroll
            for (int nt = 0; nt < 4; nt++)
                MMAH(acc[mt][nt], fa[mt], fb[nt]);
    }

    float* out = g_ctx_part + ((long)((b * HEADS + h) * NSTRIPE) + stripe) * (DH * DH);
#pragma unroll
    for (int mt = 0; mt < 2; mt++)
#pragma unroll
        for (int nt = 0; nt < 4; nt++) {
            int d0 = mt * 16 + lr, e0 = nt * 8 + lc * 2;
            out[d0 * DH + e0]           = acc[mt][nt][0];
            out[d0 * DH + e0 + 1]       = acc[mt][nt][1];
            out[(d0 + 8) * DH + e0]     = acc[mt][nt][2];
            out[(d0 + 8) * DH + e0 + 1] = acc[mt][nt][3];
        }
}

__global__ void ctx_reduce_kernel()
{
    int idx = blockIdx.x * blockDim.x + threadIdx.x;  // < B_*HEADS*1024
    int de = idx % (DH * DH);
    int bh = idx / (DH * DH);
    int d  = de / DH;
    int b  = bh / HEADS, h = bh % HEADS;
    const float* p = g_ctx_part + (long)bh * NSTRIPE * (DH * DH) + de;
    float s = 0.f;
#pragma unroll 8
    for (int st = 0; st < NSTRIPE; st++) s += p[(long)st * (DH * DH)];
    float inv = 1.f / g_ksum[b * 256 + h * DH + d];
    g_ctx[(long)bh * (DH * DH) + de] = s * inv;
}

// ---------------------------------------------------------------------------
// Fold w_out with context; emit single fp16 W2.
// ---------------------------------------------------------------------------
__global__ void fold_w2_kernel(const float* __restrict__ w_out)
{
    int idx = blockIdx.x * blockDim.x + threadIdx.x;  // < B_*256*256
    int hd = idx % 256;
    int o  = (idx / 256) % 256;
    int b  = idx / 65536;
    int h = hd / DH, d = hd % DH;
    const float* wrow = w_out + o * 256 + h * DH;
    const float* ctx  = g_ctx + ((long)(b * HEADS + h) * DH + d) * DH;
    float s = 0.f;
#pragma unroll
    for (int e = 0; e < DH; e++) s = fmaf(wrow[e], ctx[e], s);
    g_w2[(long)b * 65536 + o * 256 + hd] = __float2half(s);
}

// ---------------------------------------------------------------------------
// Launch
// ---------------------------------------------------------------------------
extern "C" void kernel_launch(void* const* d_in, const int* in_sizes, int n_in,
                              void* d_out, int out_size)
{
    const float* x     = (const float*)d_in[0];  // [2,256,32768]
    const float* w_qkv = (const float*)d_in[1];  // [768,256]
    const float* w_out = (const float*)d_in[2];  // [256,256]
    float* out = (float*)d_out;                  // [2,256,32768]

    __half *wf, *qf, *w2;
    cudaGetSymbolAddress((void**)&wf, g_wf);
    cudaGetSymbolAddress((void**)&qf, g_qf);
    cudaGetSymbolAddress((void**)&w2, g_w2);

    cudaFuncSetAttribute(gemm_tc<1>, cudaFuncAttributeMaxDynamicSharedMemorySize, GEMM_SMEM);
    cudaFuncSetAttribute(gemm_tc<0>, cudaFuncAttributeMaxDynamicSharedMemorySize, GEMM_SMEM);
    cudaFuncSetAttribute(ctx_part_kernel, cudaFuncAttributeMaxDynamicSharedMemorySize, CTX_SMEM);

    // 0) fp16 conversion of w_qkv
    cvt_half<<<(O1*CDIM/4 + 255)/256, 256>>>(w_qkv, wf, (long)O1*CDIM);

    // 1) qkv = w_qkv @ x; 1-term fp16, fused conversion + q/k/v epilogues
    gemm_tc<1><<<dim3(NTOK/BN, O1/BM, B_), 256, GEMM_SMEM>>>(
        wf, nullptr, x, nullptr, CDIM, NTOK,
        0L, (long)CDIM*NTOK, 0L);

    // 2) finish k row sums
    ksum_reduce_kernel<<<B_ * 256, 256>>>();

    // 3) partial contexts (cp.async-staged fp16 MMA, 128-token stripes)
    ctx_part_kernel<<<dim3(NSTRIPE/4, HEADS, B_), 128, CTX_SMEM>>>();

    // 4) reduce + normalize contexts
    ctx_reduce_kernel<<<(B_ * HEADS * DH * DH) / 256, 256>>>();

    // 5) fold output weight with context -> single fp16 W2
    fold_w2_kernel<<<(B_ * 256 * 256) / 256, 256>>>(w_out);

    // 6) out = W2 @ q  (1-term fp16)
    gemm_tc<0><<<dim3(NTOK/BN, CDIM/BM, B_), 256, GEMM_SMEM>>>(
        w2, qf, nullptr, out, CDIM, NTOK,
        (long)CDIM*CDIM, (long)CDIM*NTOK, (long)CDIM*NTOK);
}